// round 1
// baseline (speedup 1.0000x reference)
#include <cuda_runtime.h>
#include <math.h>

#define BB 2
#define LL 2048
#define NW 4096
#define DD 64
#define OO 128
#define NOUT 4224   // N + O
#define FTVAL 0.2f

// ---------------- scratch (device globals; no allocation allowed) ----------------
static __device__ float g_cat3[(size_t)BB * NW * 192];  // [allw | word_w_k | word_w_s]
static __device__ float g_Xk[(size_t)BB * NW * DD];
static __device__ float g_Xs[(size_t)BB * NW * DD];
static __device__ float g_F[(size_t)BB * NW * DD];      // pre-sigmoid forget (minus gate term)
static __device__ float g_U[(size_t)BB * NW * DD];      // pre-relu update (minus gate term)
static __device__ float g_Y[(size_t)BB * NW * DD];      // word_updated @ Wo + bo
static __device__ float g_cF[BB * DD];                  // gtn @ Wf[64:128]
static __device__ float g_cU[BB * DD];                  // gtn @ Wupd[0:64]
static __device__ float g_WfR[192 * DD];                // Wf rows {0:64, 128:256}
static __device__ float g_WuR[128 * DD];                // Wupd rows 64:192
static __device__ float g_cat2[(size_t)BB * OO * 128];  // [opE | word_op]
static __device__ float g_F2[(size_t)BB * OO * DD];
static __device__ float g_O2[(size_t)BB * OO * DD];

// ---------------- pack reduced weight matrices ----------------
__global__ void k_pack(const float* __restrict__ Wf, const float* __restrict__ Wupd) {
    int r = blockIdx.x;           // 0..319
    int d = threadIdx.x;          // 0..63
    if (r < 192) {
        int srcr = (r < 64) ? r : r + 64;
        g_WfR[r * DD + d] = Wf[srcr * DD + d];
    } else {
        int rr = r - 192;
        g_WuR[rr * DD + d] = Wupd[(64 + rr) * DD + d];
    }
}

// ---------------- build all_w into cat3[:, 0:64] ----------------
__global__ void __launch_bounds__(256) k_cat_allw(const float* __restrict__ w0,
                                                  const float* __restrict__ w1) {
    int r = blockIdx.x * 4 + (threadIdx.x >> 6);
    int d = threadIdx.x & 63;
    int b = r >> 12;
    int i = r & (NW - 1);
    const float* src = (i < LL) ? (w0 + ((size_t)(b * LL + i)) * DD)
                                : (w1 + ((size_t)(b * LL + i - LL)) * DD);
    g_cat3[(size_t)r * 192 + d] = src[d];
}

// ---------------- goal_trans, its l2-normalized vector, and gated GEMM constants --------
__global__ void k_prep(const float* __restrict__ nh, const float* __restrict__ Wg,
                       const float* __restrict__ bg, const float* __restrict__ Wf,
                       const float* __restrict__ Wupd) {
    int b = blockIdx.x;
    int d = threadIdx.x;
    __shared__ float gt[DD];
    __shared__ float red[DD];
    __shared__ float gtn[DD];
    float acc = bg[d];
    for (int k = 0; k < DD; k++) acc += nh[b * DD + k] * Wg[k * DD + d];
    gt[d] = acc;
    red[d] = acc * acc;
    __syncthreads();
    for (int s = 32; s > 0; s >>= 1) {
        if (d < s) red[d] += red[d + s];
        __syncthreads();
    }
    float nrm = sqrtf(red[0]);
    gtn[d] = gt[d] / (nrm + 1e-30f);
    __syncthreads();
    float cf = 0.f, cu = 0.f;
    for (int h = 0; h < DD; h++) {
        float v = gtn[h];
        cf += v * Wf[(64 + h) * DD + d];
        cu += v * Wupd[h * DD + d];
    }
    g_cF[b * DD + d] = cf;
    g_cU[b * DD + d] = cu;
}

// ---------------- generic GEMM: C[M,64] = A[M,K] @ W[K,64] + bias ----------------
// 64x64 output tile per block, 256 threads, 4x4 register blocking.
__global__ void __launch_bounds__(256) k_gemm(const float* __restrict__ A, int lda,
                                              const float* __restrict__ W,
                                              const float* __restrict__ bias,
                                              float* __restrict__ C, int K) {
    __shared__ float As[64][65];
    __shared__ float Ws[64][65];
    int tid = threadIdx.x;
    int tx = tid & 15;   // col group
    int ty = tid >> 4;   // row group
    int row0 = blockIdx.x * 64;
    float acc[4][4];
#pragma unroll
    for (int i = 0; i < 4; i++)
#pragma unroll
        for (int j = 0; j < 4; j++) acc[i][j] = 0.f;

    int lr = tid >> 2;  // load row 0..63
    int lq = tid & 3;

    for (int kt = 0; kt < K; kt += 64) {
        const float4* Ar = (const float4*)(A + (size_t)(row0 + lr) * lda + kt + lq * 16);
#pragma unroll
        for (int u = 0; u < 4; u++) {
            float4 v = Ar[u];
            int kk = lq * 16 + u * 4;
            As[lr][kk] = v.x; As[lr][kk + 1] = v.y; As[lr][kk + 2] = v.z; As[lr][kk + 3] = v.w;
        }
        const float4* Wr = (const float4*)(W + (size_t)(kt + lr) * DD + lq * 16);
#pragma unroll
        for (int u = 0; u < 4; u++) {
            float4 v = Wr[u];
            int kk = lq * 16 + u * 4;
            Ws[lr][kk] = v.x; Ws[lr][kk + 1] = v.y; Ws[lr][kk + 2] = v.z; Ws[lr][kk + 3] = v.w;
        }
        __syncthreads();
#pragma unroll
        for (int k = 0; k < 64; k++) {
            float av[4], wv[4];
#pragma unroll
            for (int i = 0; i < 4; i++) av[i] = As[ty + 16 * i][k];
#pragma unroll
            for (int j = 0; j < 4; j++) wv[j] = Ws[k][tx + 16 * j];
#pragma unroll
            for (int i = 0; i < 4; i++)
#pragma unroll
                for (int j = 0; j < 4; j++) acc[i][j] += av[i] * wv[j];
        }
        __syncthreads();
    }
#pragma unroll
    for (int j = 0; j < 4; j++) {
        int c = tx + 16 * j;
        float bv = bias ? bias[c] : 0.f;
#pragma unroll
        for (int i = 0; i < 4; i++)
            C[(size_t)(row0 + ty + 16 * i) * DD + c] = acc[i][j] + bv;
    }
}

// ---------------- word_w_k aggregation: scan ww, gather wem at ww!=0 ----------------
__global__ void __launch_bounds__(256) k_agg_k(const float* __restrict__ ww,
                                               const float* __restrict__ wem) {
    int warp = (blockIdx.x * 256 + threadIdx.x) >> 5;
    int lane = threadIdx.x & 31;
    int b = warp >> 12;
    size_t rowoff = (size_t)warp * NW;
    const float4* wwr = (const float4*)(ww + rowoff);
    const float* wemr = wem + rowoff;
    const float* X = g_Xk + (size_t)b * NW * DD;
    float a0 = 0.f, a1 = 0.f;
    int deg = 0;
    for (int kk = 0; kk < 32; kk += 8) {
        float4 v[8];
#pragma unroll
        for (int u = 0; u < 8; u++) v[u] = wwr[(size_t)(kk + u) * 32 + lane];
#pragma unroll
        for (int u = 0; u < 8; u++) {
            int m = (v[u].x != 0.f) | ((v[u].y != 0.f) << 1) |
                    ((v[u].z != 0.f) << 2) | ((v[u].w != 0.f) << 3);
#pragma unroll
            for (int e = 0; e < 4; e++) {
                unsigned bal = __ballot_sync(0xffffffffu, (m >> e) & 1);
                while (bal) {
                    int src = __ffs(bal) - 1;
                    bal &= bal - 1u;
                    int j = (kk + u) * 128 + src * 4 + e;
                    float mv = wemr[j];   // broadcast gather (all lanes same addr)
                    if (mv != 0.f) {
                        a0 += X[(size_t)j * DD + lane];
                        a1 += X[(size_t)j * DD + lane + 32];
                        deg++;
                    }
                }
            }
        }
    }
    float inv = 1.f / ((float)deg + 1e-30f);
    a0 *= inv; a1 *= inv;
    float n2 = a0 * a0 + a1 * a1;
#pragma unroll
    for (int s = 16; s; s >>= 1) n2 += __shfl_xor_sync(0xffffffffu, n2, s);
    float il = 1.f / (sqrtf(n2) + 1e-30f);
    float* dst = g_cat3 + (size_t)warp * 192 + 64;
    dst[lane] = a0 * il;
    dst[lane + 32] = a1 * il;
}

// ---------------- word_w_s aggregation over depend_0 / depend_1 ----------------
__global__ void __launch_bounds__(256) k_agg_s(const float* __restrict__ dp0,
                                               const float* __restrict__ dp1) {
    int warp = (blockIdx.x * 256 + threadIdx.x) >> 5;
    int lane = threadIdx.x & 31;
    int b = warp >> 12;
    int i = warp & (NW - 1);
    const float* mat;
    const float* X;
    if (i < LL) {
        mat = dp0 + ((size_t)(b * LL + i)) * LL;
        X = g_Xs + (size_t)b * NW * DD;
    } else {
        mat = dp1 + ((size_t)(b * LL + i - LL)) * LL;
        X = g_Xs + ((size_t)(b * NW + LL)) * DD;
    }
    const float4* m4 = (const float4*)mat;
    float a0 = 0.f, a1 = 0.f;
    int deg = 0;
    for (int kk = 0; kk < 16; kk += 8) {
        float4 v[8];
#pragma unroll
        for (int u = 0; u < 8; u++) v[u] = m4[(size_t)(kk + u) * 32 + lane];
#pragma unroll
        for (int u = 0; u < 8; u++) {
            int m = (v[u].x != 0.f) | ((v[u].y != 0.f) << 1) |
                    ((v[u].z != 0.f) << 2) | ((v[u].w != 0.f) << 3);
#pragma unroll
            for (int e = 0; e < 4; e++) {
                unsigned bal = __ballot_sync(0xffffffffu, (m >> e) & 1);
                deg += __popc(bal);
                while (bal) {
                    int src = __ffs(bal) - 1;
                    bal &= bal - 1u;
                    int j = (kk + u) * 128 + src * 4 + e;
                    a0 += X[(size_t)j * DD + lane];
                    a1 += X[(size_t)j * DD + lane + 32];
                }
            }
        }
    }
    float inv = 1.f / ((float)deg + 1e-30f);
    a0 *= inv; a1 *= inv;
    float n2 = a0 * a0 + a1 * a1;
#pragma unroll
    for (int s = 16; s; s >>= 1) n2 += __shfl_xor_sync(0xffffffffu, n2, s);
    float il = 1.f / (sqrtf(n2) + 1e-30f);
    float* dst = g_cat3 + (size_t)warp * 192 + 128;
    dst[lane] = a0 * il;
    dst[lane + 32] = a1 * il;
}

// ---------------- word update (forget gate fused with word_g gate terms) --------
__global__ void __launch_bounds__(256) k_update(const float* __restrict__ gw,
                                                float* __restrict__ out) {
    int r = blockIdx.x * 4 + (threadIdx.x >> 6);
    int d = threadIdx.x & 63;
    int b = r >> 12;
    int i = r & (NW - 1);
    float gate = (gw[b * NW + i] > 0.f) ? 1.f : 0.f;
    float pf = g_F[(size_t)r * DD + d] + gate * g_cF[b * DD + d];
    float pu = g_U[(size_t)r * DD + d] + gate * g_cU[b * DD + d];
    float f = 1.f / (1.f + __expf(-pf));
    float u = fmaxf(pu, 0.f);
    float aw = g_cat3[(size_t)r * 192 + d];
    float o = fmaxf(f, FTVAL) * aw + (1.f - f) * u;
    out[((size_t)(b * NOUT + i)) * DD + d] = o;
}

// ---------------- op aggregation: adj_op @ Y, plus build cat2 ----------------
__global__ void __launch_bounds__(256) k_agg_op(const float* __restrict__ wes,
                                                const float* __restrict__ wop,
                                                const float* __restrict__ opE) {
    int warp = (blockIdx.x * 256 + threadIdx.x) >> 5;  // 0..255 = b*O+o
    int lane = threadIdx.x & 31;
    int b = warp >> 7;
    int o = warp & (OO - 1);
    const float* Y = g_Y + (size_t)b * NW * DD;
    float a0 = 0.f, a1 = 0.f;
    int deg = 0;
    for (int base = 0; base < NW; base += 32) {
        int n = base + lane;
        float s = wes[b * NW + n];
        float w = wop[((size_t)(b * NW + n)) * OO + o];
        unsigned bal = __ballot_sync(0xffffffffu, (s != 0.f) && (w != 0.f));
        deg += __popc(bal);
        while (bal) {
            int j = base + (__ffs(bal) - 1);
            bal &= bal - 1u;
            a0 += Y[(size_t)j * DD + lane];
            a1 += Y[(size_t)j * DD + lane + 32];
        }
    }
    float inv = 1.f / ((float)deg + 1e-30f);
    float* dst = g_cat2 + (size_t)warp * 128;
    dst[64 + lane] = a0 * inv;
    dst[64 + lane + 32] = a1 * inv;
    dst[lane] = opE[(size_t)warp * DD + lane];
    dst[lane + 32] = opE[(size_t)warp * DD + lane + 32];
}

// ---------------- op output ----------------
__global__ void __launch_bounds__(256) k_opout(const float* __restrict__ opE,
                                               float* __restrict__ out) {
    int r = blockIdx.x * 4 + (threadIdx.x >> 6);  // 0..255
    int d = threadIdx.x & 63;
    int b = r >> 7;
    int o = r & (OO - 1);
    float f = 1.f / (1.f + __expf(-g_F2[(size_t)r * DD + d]));
    float u = fmaxf(g_O2[(size_t)r * DD + d], 0.f);
    float e = opE[(size_t)r * DD + d];
    out[((size_t)(b * NOUT + NW + o)) * DD + d] = fmaxf(f, FTVAL) * e + (1.f - f) * u;
}

// ---------------- launch ----------------
extern "C" void kernel_launch(void* const* d_in, const int* in_sizes, int n_in,
                              void* d_out, int out_size) {
    (void)in_sizes; (void)n_in; (void)out_size;
    const float* w0   = (const float*)d_in[0];
    const float* w1   = (const float*)d_in[1];
    const float* nh   = (const float*)d_in[2];
    const float* opE  = (const float*)d_in[3];
    const float* wes  = (const float*)d_in[4];
    const float* wem  = (const float*)d_in[5];
    const float* wop  = (const float*)d_in[6];
    const float* ww   = (const float*)d_in[7];
    const float* dp0  = (const float*)d_in[8];
    const float* dp1  = (const float*)d_in[9];
    const float* gw   = (const float*)d_in[10];
    const float* Wg   = (const float*)d_in[11];
    const float* bg   = (const float*)d_in[12];
    const float* Wwk  = (const float*)d_in[13];
    const float* bwk  = (const float*)d_in[14];
    const float* Wws  = (const float*)d_in[15];
    const float* bws  = (const float*)d_in[16];
    const float* Wo   = (const float*)d_in[17];
    const float* bo   = (const float*)d_in[18];
    const float* Wupd = (const float*)d_in[19];
    const float* bupd = (const float*)d_in[20];
    const float* Wf   = (const float*)d_in[21];
    const float* bf   = (const float*)d_in[22];
    const float* Wf2  = (const float*)d_in[23];
    const float* bf2  = (const float*)d_in[24];
    const float* Wout = (const float*)d_in[25];
    const float* bout = (const float*)d_in[26];
    float* out = (float*)d_out;

    float *cat3, *Xk, *Xs, *F, *U, *Y, *WfR, *WuR, *cat2, *F2, *O2;
    cudaGetSymbolAddress((void**)&cat3, g_cat3);
    cudaGetSymbolAddress((void**)&Xk, g_Xk);
    cudaGetSymbolAddress((void**)&Xs, g_Xs);
    cudaGetSymbolAddress((void**)&F, g_F);
    cudaGetSymbolAddress((void**)&U, g_U);
    cudaGetSymbolAddress((void**)&Y, g_Y);
    cudaGetSymbolAddress((void**)&WfR, g_WfR);
    cudaGetSymbolAddress((void**)&WuR, g_WuR);
    cudaGetSymbolAddress((void**)&cat2, g_cat2);
    cudaGetSymbolAddress((void**)&F2, g_F2);
    cudaGetSymbolAddress((void**)&O2, g_O2);

    k_pack<<<320, 64>>>(Wf, Wupd);
    k_cat_allw<<<2048, 256>>>(w0, w1);
    k_prep<<<2, 64>>>(nh, Wg, bg, Wf, Wupd);

    // Xk = all_w @ Wwk + bwk ; Xs = all_w @ Wws + bws
    k_gemm<<<128, 256>>>(cat3, 192, Wwk, bwk, Xk, 64);
    k_gemm<<<128, 256>>>(cat3, 192, Wws, bws, Xs, 64);

    // sparse aggregations write directly into cat3 slots
    k_agg_k<<<1024, 256>>>(ww, wem);
    k_agg_s<<<1024, 256>>>(dp0, dp1);

    // pre-activation forget / update GEMMs (word_g term folded into gated constants)
    k_gemm<<<128, 256>>>(cat3, 192, WfR, bf, F, 192);
    k_gemm<<<128, 256>>>(cat3 + 64, 192, WuR, bupd, U, 128);

    k_update<<<2048, 256>>>(gw, out);

    // Y = word_updated @ Wo + bo (per batch, reading rows from d_out)
    k_gemm<<<64, 256>>>(out, 64, Wo, bo, Y, 64);
    k_gemm<<<64, 256>>>(out + (size_t)NOUT * DD, 64, Wo, bo, Y + (size_t)NW * DD, 64);

    k_agg_op<<<32, 256>>>(wes, wop, opE);

    k_gemm<<<4, 256>>>(cat2, 128, Wf2, bf2, F2, 128);
    k_gemm<<<4, 256>>>(cat2 + 64, 128, Wout, bout, O2, 64);

    k_opout<<<64, 256>>>(opE, out);
}

// round 2
// speedup vs baseline: 1.0205x; 1.0205x over previous
#include <cuda_runtime.h>
#include <math.h>

#define BB 2
#define LL 2048
#define NN 4096
#define DD 64
#define OO 128
#define NOUT 4224
#define FTVAL 0.2f

typedef unsigned long long ull;

// ---------------- scratch (device globals) ----------------
static __device__ float g_c2w[(size_t)BB * NN * 128];   // [word_w_k | word_w_s]
static __device__ float g_Xk[(size_t)BB * NN * DD];
static __device__ float g_Xs[(size_t)BB * NN * DD];
static __device__ float g_Y[(size_t)BB * NN * DD];
static __device__ float g_Wfu[192 * 128];               // fused [WfR | WuR(zero-pad k<64)]
static __device__ float g_Wb2[128 * 128];               // fused [Wf2 | Wout(zero-pad k<64)]
static __device__ float g_Wx[64 * 128];                 // fused [Wwk | Wws]
static __device__ float g_cF[BB * DD];
static __device__ float g_cU[BB * DD];
static __device__ unsigned g_bits[BB * OO * 128];       // op adjacency bitmask
static __device__ float g_cat2[(size_t)BB * OO * 128];  // [opE | word_op]

// ---------------- f32x2 helpers ----------------
__device__ __forceinline__ ull dup2(float a) {
    ull d;
    asm("mov.b64 %0, {%1, %1};" : "=l"(d) : "f"(a));
    return d;
}
__device__ __forceinline__ void ffma2(ull &c, ull a, ull b) {
    asm("fma.rn.f32x2 %0, %1, %2, %3;" : "=l"(c) : "l"(a), "l"(b), "l"(c));
}
__device__ __forceinline__ float2 up2(ull v) {
    float2 f;
    asm("mov.b64 {%0, %1}, %2;" : "=f"(f.x), "=f"(f.y) : "l"(v));
    return f;
}
__device__ __forceinline__ float sigm(float x) { return 1.f / (1.f + __expf(-x)); }

// ---------------- setup: fused weights + goal constants ----------------
__global__ void k_setup(const float* __restrict__ Wf, const float* __restrict__ Wupd,
                        const float* __restrict__ Wf2, const float* __restrict__ Wout,
                        const float* __restrict__ Wwk, const float* __restrict__ Wws,
                        const float* __restrict__ nh, const float* __restrict__ Wg,
                        const float* __restrict__ bg) {
    int blk = blockIdx.x, c = threadIdx.x;
    if (blk < 192) {
        int k = blk;
        float v;
        if (c < 64) { int srcr = (k < 64) ? k : k + 64; v = Wf[srcr * 64 + c]; }
        else v = (k >= 64) ? Wupd[k * 64 + (c - 64)] : 0.f;
        g_Wfu[k * 128 + c] = v;
    } else if (blk < 320) {
        int k = blk - 192;
        float v;
        if (c < 64) v = Wf2[k * 64 + c];
        else v = (k >= 64) ? Wout[(k - 64) * 64 + (c - 64)] : 0.f;
        g_Wb2[k * 128 + c] = v;
    } else if (blk < 384) {
        int k = blk - 320;
        g_Wx[k * 128 + c] = (c < 64) ? Wwk[k * 64 + c] : Wws[k * 64 + (c - 64)];
    } else {
        int b = blk - 384;
        __shared__ float gt[64], red[64], gtn[64];
        int d = c;
        if (d < 64) {
            float acc = bg[d];
            for (int k = 0; k < 64; k++) acc += nh[b * 64 + k] * Wg[k * 64 + d];
            gt[d] = acc; red[d] = acc * acc;
        }
        __syncthreads();
        if (d == 0) { float s = 0.f; for (int k = 0; k < 64; k++) s += red[k]; red[0] = s; }
        __syncthreads();
        float nrm = sqrtf(red[0]);
        if (d < 64) gtn[d] = gt[d] / (nrm + 1e-30f);
        __syncthreads();
        if (d < 64) {
            float cf = 0.f, cu = 0.f;
            for (int h = 0; h < 64; h++) {
                float v = gtn[h];
                cf += v * Wf[(64 + h) * 64 + d];
                cu += v * Wupd[h * 64 + d];
            }
            g_cF[b * 64 + d] = cf;
            g_cU[b * 64 + d] = cu;
        }
    }
}

// ---------------- Xk|Xs GEMM: [8192,64] @ [64,128], 32-row tiles ----------------
__global__ void __launch_bounds__(256) k_gemmX(const float* __restrict__ w0,
                                               const float* __restrict__ w1,
                                               const float* __restrict__ bwk,
                                               const float* __restrict__ bws) {
    __shared__ float AsC[32 * 33];
    __shared__ float Ws[32 * 132];
    int tid = threadIdx.x;
    int r0 = blockIdx.x * 32;
    int b = r0 >> 12, i0 = r0 & (NN - 1);
    const float* Abase = (i0 < LL) ? (w0 + ((size_t)(b * LL + i0)) * DD)
                                   : (w1 + ((size_t)(b * LL + i0 - LL)) * DD);
    int tx = tid & 15, ty = tid >> 4;
    ull acc[2][4];
#pragma unroll
    for (int i = 0; i < 2; i++)
#pragma unroll
        for (int j = 0; j < 4; j++) acc[i][j] = 0ull;

    for (int kt = 0; kt < 64; kt += 32) {
        {
            int row = tid >> 3, col = (tid & 7) * 4;
            float4 v = *(const float4*)(Abase + (size_t)row * DD + kt + col);
            AsC[row * 33 + col] = v.x; AsC[row * 33 + col + 1] = v.y;
            AsC[row * 33 + col + 2] = v.z; AsC[row * 33 + col + 3] = v.w;
            int c0 = (tid & 7) * 16;
#pragma unroll
            for (int u = 0; u < 4; u++)
                *(float4*)&Ws[row * 132 + c0 + u * 4] =
                    *(const float4*)(g_Wx + (kt + row) * 128 + c0 + u * 4);
        }
        __syncthreads();
#pragma unroll
        for (int k = 0; k < 32; k++) {
            ulonglong2 p0 = *(const ulonglong2*)&Ws[k * 132 + tx * 8];
            ulonglong2 p1 = *(const ulonglong2*)&Ws[k * 132 + tx * 8 + 4];
#pragma unroll
            for (int i = 0; i < 2; i++) {
                ull a = dup2(AsC[(ty * 2 + i) * 33 + k]);
                ffma2(acc[i][0], a, p0.x);
                ffma2(acc[i][1], a, p0.y);
                ffma2(acc[i][2], a, p1.x);
                ffma2(acc[i][3], a, p1.y);
            }
        }
        __syncthreads();
    }
#pragma unroll
    for (int i = 0; i < 2; i++) {
        int rg = r0 + ty * 2 + i;
        float o[8];
#pragma unroll
        for (int j = 0; j < 4; j++) {
            float2 p = up2(acc[i][j]);
            o[2 * j] = p.x; o[2 * j + 1] = p.y;
        }
        if (tx < 8) {
            int c = tx * 8;
#pragma unroll
            for (int q = 0; q < 8; q++) o[q] += bwk[c + q];
            *(float4*)(g_Xk + (size_t)rg * 64 + c) = make_float4(o[0], o[1], o[2], o[3]);
            *(float4*)(g_Xk + (size_t)rg * 64 + c + 4) = make_float4(o[4], o[5], o[6], o[7]);
        } else {
            int c = (tx - 8) * 8;
#pragma unroll
            for (int q = 0; q < 8; q++) o[q] += bws[c + q];
            *(float4*)(g_Xs + (size_t)rg * 64 + c) = make_float4(o[0], o[1], o[2], o[3]);
            *(float4*)(g_Xs + (size_t)rg * 64 + c + 4) = make_float4(o[4], o[5], o[6], o[7]);
        }
    }
}

// ---------------- merged sparse aggregations ----------------
__global__ void __launch_bounds__(256) k_agg(const float* __restrict__ ww,
                                             const float* __restrict__ wem,
                                             const float* __restrict__ dp0,
                                             const float* __restrict__ dp1) {
    int lane = threadIdx.x & 31;
    if (blockIdx.x < 1024) {
        int warp = (blockIdx.x * 256 + threadIdx.x) >> 5;
        int b = warp >> 12;
        size_t rowoff = (size_t)warp * NN;
        const float4* wwr = (const float4*)(ww + rowoff);
        const float* wemr = wem + rowoff;
        const float* X = g_Xk + (size_t)b * NN * DD;
        float a0 = 0.f, a1 = 0.f;
        int deg = 0;
        for (int kk = 0; kk < 32; kk += 8) {
            float4 v[8];
#pragma unroll
            for (int u = 0; u < 8; u++) v[u] = wwr[(size_t)(kk + u) * 32 + lane];
#pragma unroll
            for (int u = 0; u < 8; u++) {
                int m = (v[u].x != 0.f) | ((v[u].y != 0.f) << 1) |
                        ((v[u].z != 0.f) << 2) | ((v[u].w != 0.f) << 3);
#pragma unroll
                for (int e = 0; e < 4; e++) {
                    unsigned bal = __ballot_sync(0xffffffffu, (m >> e) & 1);
                    while (bal) {
                        int src = __ffs(bal) - 1;
                        bal &= bal - 1u;
                        int j = (kk + u) * 128 + src * 4 + e;
                        float mv = wemr[j];
                        if (mv != 0.f) {
                            a0 += X[(size_t)j * DD + lane];
                            a1 += X[(size_t)j * DD + lane + 32];
                            deg++;
                        }
                    }
                }
            }
        }
        float inv = 1.f / ((float)deg + 1e-30f);
        a0 *= inv; a1 *= inv;
        float n2 = a0 * a0 + a1 * a1;
#pragma unroll
        for (int s = 16; s; s >>= 1) n2 += __shfl_xor_sync(0xffffffffu, n2, s);
        float il = 1.f / (sqrtf(n2) + 1e-30f);
        float* dst = g_c2w + (size_t)warp * 128;
        dst[lane] = a0 * il;
        dst[lane + 32] = a1 * il;
    } else {
        int warp = ((blockIdx.x - 1024) * 256 + threadIdx.x) >> 5;
        int b = warp >> 12;
        int i = warp & (NN - 1);
        const float* mat;
        const float* X;
        if (i < LL) {
            mat = dp0 + ((size_t)(b * LL + i)) * LL;
            X = g_Xs + (size_t)b * NN * DD;
        } else {
            mat = dp1 + ((size_t)(b * LL + i - LL)) * LL;
            X = g_Xs + ((size_t)(b * NN + LL)) * DD;
        }
        const float4* m4 = (const float4*)mat;
        float a0 = 0.f, a1 = 0.f;
        int deg = 0;
        for (int kk = 0; kk < 16; kk += 8) {
            float4 v[8];
#pragma unroll
            for (int u = 0; u < 8; u++) v[u] = m4[(size_t)(kk + u) * 32 + lane];
#pragma unroll
            for (int u = 0; u < 8; u++) {
                int m = (v[u].x != 0.f) | ((v[u].y != 0.f) << 1) |
                        ((v[u].z != 0.f) << 2) | ((v[u].w != 0.f) << 3);
#pragma unroll
                for (int e = 0; e < 4; e++) {
                    unsigned bal = __ballot_sync(0xffffffffu, (m >> e) & 1);
                    deg += __popc(bal);
                    while (bal) {
                        int src = __ffs(bal) - 1;
                        bal &= bal - 1u;
                        int j = (kk + u) * 128 + src * 4 + e;
                        a0 += X[(size_t)j * DD + lane];
                        a1 += X[(size_t)j * DD + lane + 32];
                    }
                }
            }
        }
        float inv = 1.f / ((float)deg + 1e-30f);
        a0 *= inv; a1 *= inv;
        float n2 = a0 * a0 + a1 * a1;
#pragma unroll
        for (int s = 16; s; s >>= 1) n2 += __shfl_xor_sync(0xffffffffu, n2, s);
        float il = 1.f / (sqrtf(n2) + 1e-30f);
        float* dst = g_c2w + (size_t)warp * 128 + 64;
        dst[lane] = a0 * il;
        dst[lane + 32] = a1 * il;
    }
}

// ---------------- fused F|U GEMM + gate/update + Y = upd @ Wo ----------------
__global__ void __launch_bounds__(256) k_fu(const float* __restrict__ w0,
                                            const float* __restrict__ w1,
                                            const float* __restrict__ gw,
                                            const float* __restrict__ bf,
                                            const float* __restrict__ bupd,
                                            const float* __restrict__ Wo,
                                            const float* __restrict__ bo,
                                            float* __restrict__ out) {
    __shared__ float SM[5280 + 2176];
    float* AsC = SM;            // [32][33]
    float* Ws = SM + 1056;      // [32][132]
    float* Ubuf = SM;           // [32][65]  (aliases AsC/Ws after main GEMM)
    float* WoS = SM;            // [64][68]  (aliases Ubuf after update phase)
    float* updS = SM + 5280;    // [32][68]
    int tid = threadIdx.x;
    int r0 = blockIdx.x * 32;
    int b = r0 >> 12, i0 = r0 & (NN - 1);
    const float* Aw = (i0 < LL) ? (w0 + ((size_t)(b * LL + i0)) * DD)
                                : (w1 + ((size_t)(b * LL + i0 - LL)) * DD);
    const float* Ac = g_c2w + (size_t)r0 * 128;
    int tx = tid & 15, ty = tid >> 4;
    ull acc[2][4];
#pragma unroll
    for (int i = 0; i < 2; i++)
#pragma unroll
        for (int j = 0; j < 4; j++) acc[i][j] = 0ull;

    for (int kt = 0; kt < 192; kt += 32) {
        {
            int row = tid >> 3, col = (tid & 7) * 4;
            float4 v;
            if (kt < 64) v = *(const float4*)(Aw + (size_t)row * DD + kt + col);
            else v = *(const float4*)(Ac + (size_t)row * 128 + (kt - 64) + col);
            AsC[row * 33 + col] = v.x; AsC[row * 33 + col + 1] = v.y;
            AsC[row * 33 + col + 2] = v.z; AsC[row * 33 + col + 3] = v.w;
            int c0 = (tid & 7) * 16;
#pragma unroll
            for (int u = 0; u < 4; u++)
                *(float4*)&Ws[row * 132 + c0 + u * 4] =
                    *(const float4*)(g_Wfu + (kt + row) * 128 + c0 + u * 4);
        }
        __syncthreads();
#pragma unroll
        for (int k = 0; k < 32; k++) {
            ulonglong2 p0 = *(const ulonglong2*)&Ws[k * 132 + tx * 8];
            ulonglong2 p1 = *(const ulonglong2*)&Ws[k * 132 + tx * 8 + 4];
#pragma unroll
            for (int i = 0; i < 2; i++) {
                ull a = dup2(AsC[(ty * 2 + i) * 33 + k]);
                ffma2(acc[i][0], a, p0.x);
                ffma2(acc[i][1], a, p0.y);
                ffma2(acc[i][2], a, p1.x);
                ffma2(acc[i][3], a, p1.y);
            }
        }
        __syncthreads();
    }
    // gate per row
    float gate[2];
#pragma unroll
    for (int i = 0; i < 2; i++)
        gate[i] = (gw[b * NN + i0 + ty * 2 + i] > 0.f) ? 1.f : 0.f;

    // epilogue phase 1: U-part -> Ubuf (relu'd)
    if (tx >= 8) {
        int c = (tx - 8) * 8;
#pragma unroll
        for (int i = 0; i < 2; i++) {
            int rloc = ty * 2 + i;
#pragma unroll
            for (int j = 0; j < 4; j++) {
                float2 p = up2(acc[i][j]);
                int cc = c + 2 * j;
                float u0 = p.x + bupd[cc] + gate[i] * g_cU[b * 64 + cc];
                float u1 = p.y + bupd[cc + 1] + gate[i] * g_cU[b * 64 + cc + 1];
                Ubuf[rloc * 65 + cc] = fmaxf(u0, 0.f);
                Ubuf[rloc * 65 + cc + 1] = fmaxf(u1, 0.f);
            }
        }
    }
    __syncthreads();
    // epilogue phase 2: forget gate, update, write out + updS
    if (tx < 8) {
        int c = tx * 8;
#pragma unroll
        for (int i = 0; i < 2; i++) {
            int rloc = ty * 2 + i;
            int iw = i0 + rloc;
            float o[8];
#pragma unroll
            for (int j = 0; j < 4; j++) {
                float2 p = up2(acc[i][j]);
#pragma unroll
                for (int h = 0; h < 2; h++) {
                    int cc = c + 2 * j + h;
                    float pre = (h ? p.y : p.x) + bf[cc] + gate[i] * g_cF[b * 64 + cc];
                    float f = sigm(pre);
                    float aw = Aw[(size_t)rloc * DD + cc];
                    float uu = Ubuf[rloc * 65 + cc];
                    float ov = fmaxf(f, FTVAL) * aw + (1.f - f) * uu;
                    updS[rloc * 68 + cc] = ov;
                    o[2 * j + h] = ov;
                }
            }
            float* dst = out + ((size_t)(b * NOUT + iw)) * 64 + c;
            *(float4*)dst = make_float4(o[0], o[1], o[2], o[3]);
            *(float4*)(dst + 4) = make_float4(o[4], o[5], o[6], o[7]);
        }
    }
    __syncthreads();
    // load Wo (overwrites Ubuf region)
    {
        int row = tid >> 2, c0 = (tid & 3) * 16;
#pragma unroll
        for (int u = 0; u < 4; u++)
            *(float4*)&WoS[row * 68 + c0 + u * 4] =
                *(const float4*)(Wo + row * 64 + c0 + u * 4);
    }
    __syncthreads();
    // Y = upd @ Wo + bo
    int tx2 = tid & 15, ty2 = tid >> 4;
    ull acc2[2][2];
    acc2[0][0] = acc2[0][1] = acc2[1][0] = acc2[1][1] = 0ull;
#pragma unroll
    for (int k = 0; k < 64; k++) {
        ulonglong2 wp = *(const ulonglong2*)&WoS[k * 68 + tx2 * 4];
#pragma unroll
        for (int i = 0; i < 2; i++) {
            ull a = dup2(updS[(ty2 * 2 + i) * 68 + k]);
            ffma2(acc2[i][0], a, wp.x);
            ffma2(acc2[i][1], a, wp.y);
        }
    }
#pragma unroll
    for (int i = 0; i < 2; i++) {
        int rg = r0 + ty2 * 2 + i;
        int c = tx2 * 4;
        float2 p0 = up2(acc2[i][0]), p1 = up2(acc2[i][1]);
        *(float4*)(g_Y + (size_t)rg * 64 + c) =
            make_float4(p0.x + bo[c], p0.y + bo[c + 1], p1.x + bo[c + 2], p1.y + bo[c + 3]);
    }
}

// ---------------- op adjacency bitmask ----------------
__global__ void __launch_bounds__(256) k_opbits(const float* __restrict__ wes,
                                                const float* __restrict__ wop) {
    int w = (blockIdx.x * 256 + threadIdx.x) >> 5;   // 0..1023
    int lane = threadIdx.x & 31;
    int b = w >> 9;
    int rem = w & 511;
    int og = rem >> 7;      // 0..3
    int ng = rem & 127;     // 0..127
    int o = og * 32 + lane;
    const float* wesb = wes + b * NN;
    unsigned word = 0;
    for (int i2 = 0; i2 < 32; i2++) {
        int n = ng * 32 + i2;
        float v = wop[((size_t)(b * NN + n)) * OO + o];
        float s = wesb[n];
        word |= ((v != 0.f && s != 0.f) ? 1u : 0u) << i2;
    }
    g_bits[((b * OO + o) << 7) + ng] = word;
}

// ---------------- op aggregation: gather Y via bitmask ----------------
__global__ void __launch_bounds__(256) k_agg_op2(const float* __restrict__ opE) {
    int rg = blockIdx.x;   // b*128 + o
    int b = rg >> 7;
    int tid = threadIdx.x, d = tid & 63, grp = tid >> 6;
    __shared__ float part[4][65];
    __shared__ int sdeg[4];
    const float* Yb = g_Y + (((size_t)b) << 12) * 64;
    unsigned base = (unsigned)rg * 128;
    float a = 0.f;
    int cnt = 0;
    for (int wi = grp; wi < 128; wi += 4) {
        unsigned bits = g_bits[base + wi];
        cnt += __popc(bits);
        while (bits) {
            int j = wi * 32 + (__ffs(bits) - 1);
            bits &= bits - 1u;
            a += Yb[(size_t)j * 64 + d];
        }
    }
    part[grp][d] = a;
    if (d == 0) sdeg[grp] = cnt;
    __syncthreads();
    if (tid < 64) {
        float s = part[0][tid] + part[1][tid] + part[2][tid] + part[3][tid];
        int deg = sdeg[0] + sdeg[1] + sdeg[2] + sdeg[3];
        float v = s / ((float)deg + 1e-30f);
        g_cat2[(size_t)rg * 128 + 64 + tid] = v;
        g_cat2[(size_t)rg * 128 + tid] = opE[(size_t)rg * 64 + tid];
    }
}

// ---------------- fused op GEMM + final gate ----------------
__global__ void __launch_bounds__(256) k_opfinal(const float* __restrict__ opE,
                                                 const float* __restrict__ bf2,
                                                 const float* __restrict__ bout,
                                                 float* __restrict__ out) {
    __shared__ float SM2[5280];
    float* AsC = SM2;
    float* Ws = SM2 + 1056;
    float* Ubuf = SM2;   // alias after GEMM
    int tid = threadIdx.x;
    int r0 = blockIdx.x * 32;
    const float* Ab = g_cat2 + (size_t)r0 * 128;
    int tx = tid & 15, ty = tid >> 4;
    ull acc[2][4];
#pragma unroll
    for (int i = 0; i < 2; i++)
#pragma unroll
        for (int j = 0; j < 4; j++) acc[i][j] = 0ull;

    for (int kt = 0; kt < 128; kt += 32) {
        {
            int row = tid >> 3, col = (tid & 7) * 4;
            float4 v = *(const float4*)(Ab + (size_t)row * 128 + kt + col);
            AsC[row * 33 + col] = v.x; AsC[row * 33 + col + 1] = v.y;
            AsC[row * 33 + col + 2] = v.z; AsC[row * 33 + col + 3] = v.w;
            int c0 = (tid & 7) * 16;
#pragma unroll
            for (int u = 0; u < 4; u++)
                *(float4*)&Ws[row * 132 + c0 + u * 4] =
                    *(const float4*)(g_Wb2 + (kt + row) * 128 + c0 + u * 4);
        }
        __syncthreads();
#pragma unroll
        for (int k = 0; k < 32; k++) {
            ulonglong2 p0 = *(const ulonglong2*)&Ws[k * 132 + tx * 8];
            ulonglong2 p1 = *(const ulonglong2*)&Ws[k * 132 + tx * 8 + 4];
#pragma unroll
            for (int i = 0; i < 2; i++) {
                ull a = dup2(AsC[(ty * 2 + i) * 33 + k]);
                ffma2(acc[i][0], a, p0.x);
                ffma2(acc[i][1], a, p0.y);
                ffma2(acc[i][2], a, p1.x);
                ffma2(acc[i][3], a, p1.y);
            }
        }
        __syncthreads();
    }
    if (tx >= 8) {
        int c = (tx - 8) * 8;
#pragma unroll
        for (int i = 0; i < 2; i++) {
            int rloc = ty * 2 + i;
#pragma unroll
            for (int j = 0; j < 4; j++) {
                float2 p = up2(acc[i][j]);
                int cc = c + 2 * j;
                Ubuf[rloc * 65 + cc] = fmaxf(p.x + bout[cc], 0.f);
                Ubuf[rloc * 65 + cc + 1] = fmaxf(p.y + bout[cc + 1], 0.f);
            }
        }
    }
    __syncthreads();
    if (tx < 8) {
        int c = tx * 8;
#pragma unroll
        for (int i = 0; i < 2; i++) {
            int rloc = ty * 2 + i;
            int rg = r0 + rloc;
            int b = rg >> 7, oo = rg & (OO - 1);
            float o[8];
#pragma unroll
            for (int j = 0; j < 4; j++) {
                float2 p = up2(acc[i][j]);
#pragma unroll
                for (int h = 0; h < 2; h++) {
                    int cc = c + 2 * j + h;
                    float f = sigm((h ? p.y : p.x) + bf2[cc]);
                    float e = opE[(size_t)rg * 64 + cc];
                    float uu = Ubuf[rloc * 65 + cc];
                    o[2 * j + h] = fmaxf(f, FTVAL) * e + (1.f - f) * uu;
                }
            }
            float* dst = out + ((size_t)(b * NOUT + NN + oo)) * 64 + c;
            *(float4*)dst = make_float4(o[0], o[1], o[2], o[3]);
            *(float4*)(dst + 4) = make_float4(o[4], o[5], o[6], o[7]);
        }
    }
}

// ---------------- launch ----------------
extern "C" void kernel_launch(void* const* d_in, const int* in_sizes, int n_in,
                              void* d_out, int out_size) {
    (void)in_sizes; (void)n_in; (void)out_size;
    const float* w0   = (const float*)d_in[0];
    const float* w1   = (const float*)d_in[1];
    const float* nh   = (const float*)d_in[2];
    const float* opE  = (const float*)d_in[3];
    const float* wes  = (const float*)d_in[4];
    const float* wem  = (const float*)d_in[5];
    const float* wop  = (const float*)d_in[6];
    const float* ww   = (const float*)d_in[7];
    const float* dp0  = (const float*)d_in[8];
    const float* dp1  = (const float*)d_in[9];
    const float* gw   = (const float*)d_in[10];
    const float* Wg   = (const float*)d_in[11];
    const float* bg   = (const float*)d_in[12];
    const float* Wwk  = (const float*)d_in[13];
    const float* bwk  = (const float*)d_in[14];
    const float* Wws  = (const float*)d_in[15];
    const float* bws  = (const float*)d_in[16];
    const float* Wo   = (const float*)d_in[17];
    const float* bo   = (const float*)d_in[18];
    const float* Wupd = (const float*)d_in[19];
    const float* bupd = (const float*)d_in[20];
    const float* Wf   = (const float*)d_in[21];
    const float* bf   = (const float*)d_in[22];
    const float* Wf2  = (const float*)d_in[23];
    const float* bf2  = (const float*)d_in[24];
    const float* Wout = (const float*)d_in[25];
    const float* bout = (const float*)d_in[26];
    float* out = (float*)d_out;

    k_setup<<<386, 128>>>(Wf, Wupd, Wf2, Wout, Wwk, Wws, nh, Wg, bg);
    k_opbits<<<128, 256>>>(wes, wop);
    k_gemmX<<<256, 256>>>(w0, w1, bwk, bws);
    k_agg<<<2048, 256>>>(ww, wem, dp0, dp1);
    k_fu<<<256, 256>>>(w0, w1, gw, bf, bupd, Wo, bo, out);
    k_agg_op2<<<256, 256>>>(opE);
    k_opfinal<<<8, 256>>>(opE, bf2, bout, out);
}

// round 3
// speedup vs baseline: 2.2158x; 2.1712x over previous
#include <cuda_runtime.h>
#include <math.h>

#define LL 2048
#define NN 4096
#define OO 128
#define NOUT 4224
#define FTVAL 0.2f

typedef unsigned long long ull;

// ---------------- scratch ----------------
static __device__ float g_aggK[(size_t)2 * NN * 64];
static __device__ float g_aggS[(size_t)2 * NN * 64];
static __device__ float g_gateK[2 * NN];
static __device__ float g_gateS[2 * NN];
static __device__ float g_Y[(size_t)2 * NN * 64];
static __device__ float g_Wx[64 * 128];     // [Wwk | Wws]
static __device__ float g_Wfu[192 * 128];   // [WfR | WuR]
static __device__ float g_Wb2[128 * 128];   // [Wf2 | Wout(pad)]
static __device__ float g_cF[2 * 64];
static __device__ float g_cU[2 * 64];
static __device__ unsigned g_bits[2 * OO * 128];
static __device__ float g_cat2[(size_t)2 * OO * 128];

// ---------------- helpers ----------------
__device__ __forceinline__ ull dup2(float a) {
    ull d; asm("mov.b64 %0, {%1, %1};" : "=l"(d) : "f"(a)); return d;
}
__device__ __forceinline__ void ffma2(ull &c, ull a, ull b) {
    asm("fma.rn.f32x2 %0, %1, %2, %3;" : "=l"(c) : "l"(a), "l"(b), "l"(c));
}
__device__ __forceinline__ float2 up2(ull v) {
    float2 f; asm("mov.b64 {%0, %1}, %2;" : "=f"(f.x), "=f"(f.y) : "l"(v)); return f;
}
__device__ __forceinline__ float sigm(float x) { return 1.f / (1.f + __expf(-x)); }

// ---------------- setup ----------------
__global__ void k_setup(const float* __restrict__ Wf, const float* __restrict__ Wupd,
                        const float* __restrict__ Wf2, const float* __restrict__ Wout,
                        const float* __restrict__ Wwk, const float* __restrict__ Wws,
                        const float* __restrict__ nh, const float* __restrict__ Wg,
                        const float* __restrict__ bg) {
    int blk = blockIdx.x, c = threadIdx.x;
    if (blk < 192) {
        int k = blk;
        float v;
        if (c < 64) { int srcr = (k < 64) ? k : k + 64; v = Wf[srcr * 64 + c]; }
        else v = (k >= 64) ? Wupd[k * 64 + (c - 64)] : 0.f;
        g_Wfu[k * 128 + c] = v;
    } else if (blk < 320) {
        int k = blk - 192;
        float v;
        if (c < 64) v = Wf2[k * 64 + c];
        else v = (k >= 64) ? Wout[(k - 64) * 64 + (c - 64)] : 0.f;
        g_Wb2[k * 128 + c] = v;
    } else if (blk < 384) {
        int k = blk - 320;
        g_Wx[k * 128 + c] = (c < 64) ? Wwk[k * 64 + c] : Wws[k * 64 + (c - 64)];
    } else {
        int b = blk - 384;
        __shared__ float gt[64], red[64], gtn[64];
        int d = c;
        if (d < 64) {
            float acc = bg[d];
            for (int k = 0; k < 64; k++) acc += nh[b * 64 + k] * Wg[k * 64 + d];
            gt[d] = acc; red[d] = acc * acc;
        }
        __syncthreads();
        if (d == 0) { float s = 0.f; for (int k = 0; k < 64; k++) s += red[k]; red[0] = s; }
        __syncthreads();
        float nrm = sqrtf(red[0]);
        if (d < 64) gtn[d] = gt[d] / (nrm + 1e-30f);
        __syncthreads();
        if (d < 64) {
            float cf = 0.f, cu = 0.f;
            for (int h = 0; h < 64; h++) {
                float v = gtn[h];
                cf += v * Wf[(64 + h) * 64 + d];
                cu += v * Wupd[h * 64 + d];
            }
            g_cF[b * 64 + d] = cf;
            g_cU[b * 64 + d] = cu;
        }
    }
}

// ---------------- sparse aggregations: compact-then-gather ----------------
__global__ void __launch_bounds__(256) k_agg(const float* __restrict__ ww,
                                             const float* __restrict__ wem,
                                             const float* __restrict__ dp0,
                                             const float* __restrict__ dp1,
                                             const float* __restrict__ w0,
                                             const float* __restrict__ w1) {
    __shared__ int buf[8][256];
    int wip = threadIdx.x >> 5, lane = threadIdx.x & 31;
    unsigned ltm = (1u << lane) - 1u;
    int* B = buf[wip];

    if (blockIdx.x < 1024) {
        // ---- word_w_k task: scan ww, filter by wem, gather w0/w1 rows ----
        int row = blockIdx.x * 8 + wip;       // 0..8191
        int b = row >> 12;
        const float4* wwr = (const float4*)(ww + (size_t)row * NN);
        const float* wemr = wem + (size_t)row * NN;
        const float* w0b = w0 + ((size_t)b * LL) * 64;
        const float* w1b = w1 + ((size_t)b * LL) * 64;
        int cnt = 0;
        for (int kk = 0; kk < 32; kk += 8) {
            float4 v[8];
#pragma unroll
            for (int u = 0; u < 8; u++) v[u] = wwr[(size_t)(kk + u) * 32 + lane];
#pragma unroll
            for (int u = 0; u < 8; u++) {
                int m = (v[u].x != 0.f) | ((v[u].y != 0.f) << 1) |
                        ((v[u].z != 0.f) << 2) | ((v[u].w != 0.f) << 3);
#pragma unroll
                for (int e = 0; e < 4; e++) {
                    unsigned bal = __ballot_sync(0xffffffffu, (m >> e) & 1);
                    int pos = cnt + __popc(bal & ltm);
                    if (((m >> e) & 1) && pos < 256)
                        B[pos] = (kk + u) * 128 + lane * 4 + e;
                    cnt += __popc(bal);
                }
            }
        }
        if (cnt > 256) cnt = 256;
        __syncwarp();
        // filter by wem (lane-parallel gathers, re-compact)
        int cnt2 = 0;
        for (int base = 0; base < cnt; base += 32) {
            int t = base + lane;
            int j = (t < cnt) ? B[t] : -1;
            bool val = (j >= 0) && (wemr[j] != 0.f);
            unsigned bal = __ballot_sync(0xffffffffu, val);
            __syncwarp();
            if (val) B[cnt2 + __popc(bal & ltm)] = j;
            cnt2 += __popc(bal);
        }
        __syncwarp();
        // gather, 4-way unrolled
        float a0 = 0.f, a1 = 0.f, c0 = 0.f, c1 = 0.f;
        int t = 0;
        for (; t + 4 <= cnt2; t += 4) {
            int j0 = B[t], j1 = B[t + 1], j2 = B[t + 2], j3 = B[t + 3];
            const float* p0 = (j0 < LL) ? w0b + (size_t)j0 * 64 : w1b + (size_t)(j0 - LL) * 64;
            const float* p1 = (j1 < LL) ? w0b + (size_t)j1 * 64 : w1b + (size_t)(j1 - LL) * 64;
            const float* p2 = (j2 < LL) ? w0b + (size_t)j2 * 64 : w1b + (size_t)(j2 - LL) * 64;
            const float* p3 = (j3 < LL) ? w0b + (size_t)j3 * 64 : w1b + (size_t)(j3 - LL) * 64;
            float x0 = p0[lane], x1 = p1[lane], x2 = p2[lane], x3 = p3[lane];
            float y0 = p0[lane + 32], y1 = p1[lane + 32], y2 = p2[lane + 32], y3 = p3[lane + 32];
            a0 += x0; c0 += x1; a0 += x2; c0 += x3;
            a1 += y0; c1 += y1; a1 += y2; c1 += y3;
        }
        for (; t < cnt2; t++) {
            int j = B[t];
            const float* p = (j < LL) ? w0b + (size_t)j * 64 : w1b + (size_t)(j - LL) * 64;
            a0 += p[lane]; a1 += p[lane + 32];
        }
        a0 += c0; a1 += c1;
        float inv = 1.f / ((float)cnt2 + 1e-30f);
        g_aggK[(size_t)row * 64 + lane] = a0 * inv;
        g_aggK[(size_t)row * 64 + lane + 32] = a1 * inv;
        if (lane == 0) g_gateK[row] = (cnt2 > 0) ? 1.f : 0.f;
    } else {
        // ---- word_w_s task: scan depend, gather w0 or w1 rows ----
        int row = (blockIdx.x - 1024) * 8 + wip;  // 0..8191
        int b = row >> 12;
        int i = row & (NN - 1);
        const float* mat;
        const float* Xb;
        if (i < LL) {
            mat = dp0 + ((size_t)(b * LL + i)) * LL;
            Xb = w0 + ((size_t)b * LL) * 64;
        } else {
            mat = dp1 + ((size_t)(b * LL + i - LL)) * LL;
            Xb = w1 + ((size_t)b * LL) * 64;
        }
        const float4* m4 = (const float4*)mat;
        int cnt = 0;
        for (int kk = 0; kk < 16; kk += 8) {
            float4 v[8];
#pragma unroll
            for (int u = 0; u < 8; u++) v[u] = m4[(size_t)(kk + u) * 32 + lane];
#pragma unroll
            for (int u = 0; u < 8; u++) {
                int m = (v[u].x != 0.f) | ((v[u].y != 0.f) << 1) |
                        ((v[u].z != 0.f) << 2) | ((v[u].w != 0.f) << 3);
#pragma unroll
                for (int e = 0; e < 4; e++) {
                    unsigned bal = __ballot_sync(0xffffffffu, (m >> e) & 1);
                    int pos = cnt + __popc(bal & ltm);
                    if (((m >> e) & 1) && pos < 256)
                        B[pos] = (kk + u) * 128 + lane * 4 + e;
                    cnt += __popc(bal);
                }
            }
        }
        if (cnt > 256) cnt = 256;
        __syncwarp();
        float a0 = 0.f, a1 = 0.f, c0 = 0.f, c1 = 0.f;
        int t = 0;
        for (; t + 4 <= cnt; t += 4) {
            int j0 = B[t], j1 = B[t + 1], j2 = B[t + 2], j3 = B[t + 3];
            const float* p0 = Xb + (size_t)j0 * 64;
            const float* p1 = Xb + (size_t)j1 * 64;
            const float* p2 = Xb + (size_t)j2 * 64;
            const float* p3 = Xb + (size_t)j3 * 64;
            float x0 = p0[lane], x1 = p1[lane], x2 = p2[lane], x3 = p3[lane];
            float y0 = p0[lane + 32], y1 = p1[lane + 32], y2 = p2[lane + 32], y3 = p3[lane + 32];
            a0 += x0; c0 += x1; a0 += x2; c0 += x3;
            a1 += y0; c1 += y1; a1 += y2; c1 += y3;
        }
        for (; t < cnt; t++) {
            const float* p = Xb + (size_t)B[t] * 64;
            a0 += p[lane]; a1 += p[lane + 32];
        }
        a0 += c0; a1 += c1;
        float inv = 1.f / ((float)cnt + 1e-30f);
        g_aggS[(size_t)row * 64 + lane] = a0 * inv;
        g_aggS[(size_t)row * 64 + lane + 32] = a1 * inv;
        if (lane == 0) g_gateS[row] = (cnt > 0) ? 1.f : 0.f;
    }
}

// ---------------- fused: X-GEMM + l2n + FU-GEMM + update + Y-GEMM ----------------
__global__ void __launch_bounds__(256) k_fu(const float* __restrict__ w0,
                                            const float* __restrict__ w1,
                                            const float* __restrict__ gw,
                                            const float* __restrict__ bwk,
                                            const float* __restrict__ bws,
                                            const float* __restrict__ bf,
                                            const float* __restrict__ bupd,
                                            const float* __restrict__ Wo,
                                            const float* __restrict__ bo,
                                            float* __restrict__ out) {
    __shared__ float SM[10752];
    float* R1 = SM;           // AsK (A) / As-allw (B,C), stride 68
    float* R2 = SM + 2176;    // AsS (A) / updS (B,C), stride 68
    float* WcS = SM + 4352;   // weight chunk 16x128
    float* R4 = SM + 6400;    // C2 stride 128 (A,B) / WoS stride 68 (C)

    int tid = threadIdx.x;
    int tx = tid & 15, ty = tid >> 4;
    int r0 = blockIdx.x * 32;
    int b = r0 >> 12, i0 = r0 & (NN - 1);

    // load AsK / AsS tiles
    {
        int row = tid >> 3, col = (tid & 7) * 8;
        const float* sK = g_aggK + (size_t)(r0 + row) * 64 + col;
        const float* sS = g_aggS + (size_t)(r0 + row) * 64 + col;
        *(float4*)&R1[row * 68 + col] = *(const float4*)sK;
        *(float4*)&R1[row * 68 + col + 4] = *(const float4*)(sK + 4);
        *(float4*)&R2[row * 68 + col] = *(const float4*)sS;
        *(float4*)&R2[row * 68 + col + 4] = *(const float4*)(sS + 4);
    }

    ull acc[2][4];
#pragma unroll
    for (int i = 0; i < 2; i++)
#pragma unroll
        for (int j = 0; j < 4; j++) acc[i][j] = 0ull;

    // ---- phase A: [aggK|aggS] @ [Wwk|Wws] ----
    for (int kt = 0; kt < 64; kt += 16) {
        __syncthreads();
        {
            int row = tid >> 4, col = (tid & 15) * 8;
            *(float4*)&WcS[row * 128 + col] = *(const float4*)(g_Wx + (kt + row) * 128 + col);
            *(float4*)&WcS[row * 128 + col + 4] = *(const float4*)(g_Wx + (kt + row) * 128 + col + 4);
        }
        __syncthreads();
#pragma unroll
        for (int k = 0; k < 16; k++) {
            ulonglong2 p0 = *(const ulonglong2*)&WcS[k * 128 + tx * 4];
            ulonglong2 p1 = *(const ulonglong2*)&WcS[k * 128 + 64 + tx * 4];
#pragma unroll
            for (int i = 0; i < 2; i++) {
                int r = ty * 2 + i;
                ull ak = dup2(R1[r * 68 + kt + k]);
                ull as = dup2(R2[r * 68 + kt + k]);
                ffma2(acc[i][0], ak, p0.x);
                ffma2(acc[i][1], ak, p0.y);
                ffma2(acc[i][2], as, p1.x);
                ffma2(acc[i][3], as, p1.y);
            }
        }
    }
    // epilogue A: bias-gate + l2n -> C2 (R4)
#pragma unroll
    for (int i = 0; i < 2; i++) {
        int r = ty * 2 + i;
        float gk = g_gateK[r0 + r], gs = g_gateS[r0 + r];
        float wk[4], ws[4];
#pragma unroll
        for (int j = 0; j < 2; j++) {
            float2 pk = up2(acc[i][j]);
            float2 ps = up2(acc[i][2 + j]);
            int c = tx * 4 + 2 * j;
            wk[2 * j] = pk.x + gk * bwk[c];
            wk[2 * j + 1] = pk.y + gk * bwk[c + 1];
            ws[2 * j] = ps.x + gs * bws[c];
            ws[2 * j + 1] = ps.y + gs * bws[c + 1];
        }
        float sk = 0.f, ss = 0.f;
#pragma unroll
        for (int q = 0; q < 4; q++) { sk += wk[q] * wk[q]; ss += ws[q] * ws[q]; }
#pragma unroll
        for (int d = 8; d; d >>= 1) {
            sk += __shfl_xor_sync(0xffffffffu, sk, d);
            ss += __shfl_xor_sync(0xffffffffu, ss, d);
        }
        float ik = 1.f / (sqrtf(sk) + 1e-30f);
        float is = 1.f / (sqrtf(ss) + 1e-30f);
        *(float4*)&R4[r * 128 + tx * 4] =
            make_float4(wk[0] * ik, wk[1] * ik, wk[2] * ik, wk[3] * ik);
        *(float4*)&R4[r * 128 + 64 + tx * 4] =
            make_float4(ws[0] * is, ws[1] * is, ws[2] * is, ws[3] * is);
    }
    __syncthreads();
    // load allw tile into R1
    {
        int row = tid >> 3, col = (tid & 7) * 8;
        int i = i0 + row;
        const float* src = (i < LL) ? (w0 + ((size_t)(b * LL + i)) * 64)
                                    : (w1 + ((size_t)(b * LL + i - LL)) * 64);
        *(float4*)&R1[row * 68 + col] = *(const float4*)(src + col);
        *(float4*)&R1[row * 68 + col + 4] = *(const float4*)(src + col + 4);
    }
#pragma unroll
    for (int i = 0; i < 2; i++)
#pragma unroll
        for (int j = 0; j < 4; j++) acc[i][j] = 0ull;

    // ---- phase B: [allw|wk|ws] @ Wfu ----
    for (int kt = 0; kt < 192; kt += 16) {
        __syncthreads();
        {
            int row = tid >> 4, col = (tid & 15) * 8;
            *(float4*)&WcS[row * 128 + col] = *(const float4*)(g_Wfu + (kt + row) * 128 + col);
            *(float4*)&WcS[row * 128 + col + 4] = *(const float4*)(g_Wfu + (kt + row) * 128 + col + 4);
        }
        __syncthreads();
        const float* arow0 = (kt < 64) ? &R1[(ty * 2) * 68 + kt] : &R4[(ty * 2) * 128 + kt - 64];
        const float* arow1 = (kt < 64) ? &R1[(ty * 2 + 1) * 68 + kt] : &R4[(ty * 2 + 1) * 128 + kt - 64];
#pragma unroll
        for (int k = 0; k < 16; k++) {
            ulonglong2 p0 = *(const ulonglong2*)&WcS[k * 128 + tx * 4];
            ulonglong2 p1 = *(const ulonglong2*)&WcS[k * 128 + 64 + tx * 4];
            ull a0 = dup2(arow0[k]);
            ull a1 = dup2(arow1[k]);
            ffma2(acc[0][0], a0, p0.x);
            ffma2(acc[0][1], a0, p0.y);
            ffma2(acc[0][2], a0, p1.x);
            ffma2(acc[0][3], a0, p1.y);
            ffma2(acc[1][0], a1, p0.x);
            ffma2(acc[1][1], a1, p0.y);
            ffma2(acc[1][2], a1, p1.x);
            ffma2(acc[1][3], a1, p1.y);
        }
    }
    __syncthreads();
    // epilogue B: gates + update, write out + updS (R2)
#pragma unroll
    for (int i = 0; i < 2; i++) {
        int r = ty * 2 + i;
        int iw = i0 + r;
        float gate = (gw[b * NN + iw] > 0.f) ? 1.f : 0.f;
        float o[4];
#pragma unroll
        for (int j = 0; j < 2; j++) {
            float2 pf = up2(acc[i][j]);
            float2 pu = up2(acc[i][2 + j]);
#pragma unroll
            for (int h = 0; h < 2; h++) {
                int c = tx * 4 + 2 * j + h;
                float fv = sigm((h ? pf.y : pf.x) + bf[c] + gate * g_cF[b * 64 + c]);
                float uv = fmaxf((h ? pu.y : pu.x) + bupd[c] + gate * g_cU[b * 64 + c], 0.f);
                float aw = R1[r * 68 + c];
                o[2 * j + h] = fmaxf(fv, FTVAL) * aw + (1.f - fv) * uv;
            }
        }
        *(float4*)(out + ((size_t)(b * NOUT + iw)) * 64 + tx * 4) =
            make_float4(o[0], o[1], o[2], o[3]);
        *(float4*)&R2[r * 68 + tx * 4] = make_float4(o[0], o[1], o[2], o[3]);
    }
    __syncthreads();
    // ---- phase C: Y = upd @ Wo + bo ----
    {
        int row = tid >> 2, col = (tid & 3) * 16;
#pragma unroll
        for (int u = 0; u < 4; u++)
            *(float4*)&R4[row * 68 + col + u * 4] = *(const float4*)(Wo + row * 64 + col + u * 4);
    }
    __syncthreads();
    ull acc2[2][2];
    acc2[0][0] = acc2[0][1] = acc2[1][0] = acc2[1][1] = 0ull;
#pragma unroll
    for (int k = 0; k < 64; k++) {
        ulonglong2 wp = *(const ulonglong2*)&R4[k * 68 + tx * 4];
        ull a0 = dup2(R2[(ty * 2) * 68 + k]);
        ull a1 = dup2(R2[(ty * 2 + 1) * 68 + k]);
        ffma2(acc2[0][0], a0, wp.x);
        ffma2(acc2[0][1], a0, wp.y);
        ffma2(acc2[1][0], a1, wp.x);
        ffma2(acc2[1][1], a1, wp.y);
    }
#pragma unroll
    for (int i = 0; i < 2; i++) {
        int rg = r0 + ty * 2 + i;
        int c = tx * 4;
        float2 p0 = up2(acc2[i][0]), p1 = up2(acc2[i][1]);
        *(float4*)(g_Y + (size_t)rg * 64 + c) =
            make_float4(p0.x + bo[c], p0.y + bo[c + 1], p1.x + bo[c + 2], p1.y + bo[c + 3]);
    }
}

// ---------------- op adjacency bitmask ----------------
__global__ void __launch_bounds__(256) k_opbits(const float* __restrict__ wes,
                                                const float* __restrict__ wop) {
    int w = (blockIdx.x * 256 + threadIdx.x) >> 5;
    int lane = threadIdx.x & 31;
    int b = w >> 9;
    int rem = w & 511;
    int og = rem >> 7;
    int ng = rem & 127;
    int o = og * 32 + lane;
    const float* wesb = wes + b * NN;
    unsigned word = 0;
    for (int i2 = 0; i2 < 32; i2++) {
        int n = ng * 32 + i2;
        float v = wop[((size_t)(b * NN + n)) * OO + o];
        float s = wesb[n];
        word |= ((v != 0.f && s != 0.f) ? 1u : 0u) << i2;
    }
    g_bits[((b * OO + o) << 7) + ng] = word;
}

// ---------------- op aggregation ----------------
__global__ void __launch_bounds__(256) k_agg_op2(const float* __restrict__ opE) {
    int rg = blockIdx.x;
    int b = rg >> 7;
    int tid = threadIdx.x, d = tid & 63, grp = tid >> 6;
    __shared__ float part[4][65];
    __shared__ int sdeg[4];
    const float* Yb = g_Y + (((size_t)b) << 12) * 64;
    unsigned base = (unsigned)rg * 128;
    float a = 0.f;
    int cnt = 0;
    for (int wi = grp; wi < 128; wi += 4) {
        unsigned bits = g_bits[base + wi];
        cnt += __popc(bits);
        while (bits) {
            int j = wi * 32 + (__ffs(bits) - 1);
            bits &= bits - 1u;
            a += Yb[(size_t)j * 64 + d];
        }
    }
    part[grp][d] = a;
    if (d == 0) sdeg[grp] = cnt;
    __syncthreads();
    if (tid < 64) {
        float s = part[0][tid] + part[1][tid] + part[2][tid] + part[3][tid];
        int deg = sdeg[0] + sdeg[1] + sdeg[2] + sdeg[3];
        g_cat2[(size_t)rg * 128 + 64 + tid] = s / ((float)deg + 1e-30f);
        g_cat2[(size_t)rg * 128 + tid] = opE[(size_t)rg * 64 + tid];
    }
}

// ---------------- op final: fused GEMM + gates (register epilogue) ----------------
__global__ void __launch_bounds__(256) k_opfinal(const float* __restrict__ opE,
                                                 const float* __restrict__ bf2,
                                                 const float* __restrict__ bout,
                                                 float* __restrict__ out) {
    __shared__ float Asm[32 * 132];
    __shared__ float WcS[16 * 128];
    int tid = threadIdx.x, tx = tid & 15, ty = tid >> 4;
    int r0 = blockIdx.x * 32;
    {
        int row = tid >> 3, col = (tid & 7) * 16;
#pragma unroll
        for (int u = 0; u < 4; u++)
            *(float4*)&Asm[row * 132 + col + u * 4] =
                *(const float4*)(g_cat2 + (size_t)(r0 + row) * 128 + col + u * 4);
    }
    ull acc[2][4];
#pragma unroll
    for (int i = 0; i < 2; i++)
#pragma unroll
        for (int j = 0; j < 4; j++) acc[i][j] = 0ull;
    for (int kt = 0; kt < 128; kt += 16) {
        __syncthreads();
        {
            int row = tid >> 4, col = (tid & 15) * 8;
            *(float4*)&WcS[row * 128 + col] = *(const float4*)(g_Wb2 + (kt + row) * 128 + col);
            *(float4*)&WcS[row * 128 + col + 4] = *(const float4*)(g_Wb2 + (kt + row) * 128 + col + 4);
        }
        __syncthreads();
#pragma unroll
        for (int k = 0; k < 16; k++) {
            ulonglong2 p0 = *(const ulonglong2*)&WcS[k * 128 + tx * 4];
            ulonglong2 p1 = *(const ulonglong2*)&WcS[k * 128 + 64 + tx * 4];
#pragma unroll
            for (int i = 0; i < 2; i++) {
                ull a = dup2(Asm[(ty * 2 + i) * 132 + kt + k]);
                ffma2(acc[i][0], a, p0.x);
                ffma2(acc[i][1], a, p0.y);
                ffma2(acc[i][2], a, p1.x);
                ffma2(acc[i][3], a, p1.y);
            }
        }
    }
#pragma unroll
    for (int i = 0; i < 2; i++) {
        int rg = r0 + ty * 2 + i;
        int bq = rg >> 7, oo = rg & (OO - 1);
        float4 e4 = *(const float4*)(opE + (size_t)rg * 64 + tx * 4);
        float ev[4] = {e4.x, e4.y, e4.z, e4.w};
        float o[4];
#pragma unroll
        for (int j = 0; j < 2; j++) {
            float2 pf = up2(acc[i][j]);
            float2 pu = up2(acc[i][2 + j]);
#pragma unroll
            for (int h = 0; h < 2; h++) {
                int c = tx * 4 + 2 * j + h;
                float fv = sigm((h ? pf.y : pf.x) + bf2[c]);
                float uv = fmaxf((h ? pu.y : pu.x) + bout[c], 0.f);
                o[2 * j + h] = fmaxf(fv, FTVAL) * ev[2 * j + h] + (1.f - fv) * uv;
            }
        }
        *(float4*)(out + ((size_t)(bq * NOUT + NN + oo)) * 64 + tx * 4) =
            make_float4(o[0], o[1], o[2], o[3]);
    }
}

// ---------------- launch ----------------
extern "C" void kernel_launch(void* const* d_in, const int* in_sizes, int n_in,
                              void* d_out, int out_size) {
    (void)in_sizes; (void)n_in; (void)out_size;
    const float* w0   = (const float*)d_in[0];
    const float* w1   = (const float*)d_in[1];
    const float* nh   = (const float*)d_in[2];
    const float* opE  = (const float*)d_in[3];
    const float* wes  = (const float*)d_in[4];
    const float* wem  = (const float*)d_in[5];
    const float* wop  = (const float*)d_in[6];
    const float* ww   = (const float*)d_in[7];
    const float* dp0  = (const float*)d_in[8];
    const float* dp1  = (const float*)d_in[9];
    const float* gw   = (const float*)d_in[10];
    const float* Wg   = (const float*)d_in[11];
    const float* bg   = (const float*)d_in[12];
    const float* Wwk  = (const float*)d_in[13];
    const float* bwk  = (const float*)d_in[14];
    const float* Wws  = (const float*)d_in[15];
    const float* bws  = (const float*)d_in[16];
    const float* Wo   = (const float*)d_in[17];
    const float* bo   = (const float*)d_in[18];
    const float* Wupd = (const float*)d_in[19];
    const float* bupd = (const float*)d_in[20];
    const float* Wf   = (const float*)d_in[21];
    const float* bf   = (const float*)d_in[22];
    const float* Wf2  = (const float*)d_in[23];
    const float* bf2  = (const float*)d_in[24];
    const float* Wout = (const float*)d_in[25];
    const float* bout = (const float*)d_in[26];
    float* out = (float*)d_out;

    k_setup<<<386, 128>>>(Wf, Wupd, Wf2, Wout, Wwk, Wws, nh, Wg, bg);
    k_opbits<<<128, 256>>>(wes, wop);
    k_agg<<<2048, 256>>>(ww, wem, dp0, dp1, w0, w1);
    k_fu<<<256, 256>>>(w0, w1, gw, bwk, bws, bf, bupd, Wo, bo, out);
    k_agg_op2<<<256, 256>>>(opE);
    k_opfinal<<<8, 256>>>(opE, bf2, bout, out);
}

// round 5
// speedup vs baseline: 2.4733x; 1.1162x over previous
#include <cuda_runtime.h>
#include <math.h>

#define LL 2048
#define NN 4096
#define OO 128
#define NOUT 4224
#define FTVAL 0.2f

typedef unsigned long long ull;

// ---------------- scratch ----------------
static __device__ float g_aggK[(size_t)2 * NN * 64];
static __device__ float g_aggS[(size_t)2 * NN * 64];
static __device__ float g_gateK[2 * NN];
static __device__ float g_gateS[2 * NN];
static __device__ float g_Y[(size_t)2 * NN * 64];
static __device__ float g_Wx[64 * 128];     // [Wwk | Wws]
static __device__ float g_Wfu[192 * 128];   // [WfR | WuR]
static __device__ float g_Wb2[128 * 128];   // [Wf2 | Wout(pad)]
static __device__ float g_cF[2 * 64];
static __device__ float g_cU[2 * 64];
static __device__ unsigned g_bits[2 * OO * 128];
static __device__ float g_cat2[(size_t)2 * OO * 128];

// ---------------- helpers ----------------
__device__ __forceinline__ ull dup2(float a) {
    ull d; asm("mov.b64 %0, {%1, %1};" : "=l"(d) : "f"(a)); return d;
}
__device__ __forceinline__ void ffma2(ull &c, ull a, ull b) {
    asm("fma.rn.f32x2 %0, %1, %2, %3;" : "=l"(c) : "l"(a), "l"(b), "l"(c));
}
__device__ __forceinline__ float2 up2(ull v) {
    float2 f; asm("mov.b64 {%0, %1}, %2;" : "=f"(f.x), "=f"(f.y) : "l"(v)); return f;
}
__device__ __forceinline__ float sigm(float x) { return 1.f / (1.f + __expf(-x)); }

// ================= mega kernel: setup (193) + opbits (128) + agg (2048) =================
__global__ void __launch_bounds__(256) k_mega(
        const float* __restrict__ ww, const float* __restrict__ wem,
        const float* __restrict__ dp0, const float* __restrict__ dp1,
        const float* __restrict__ w0, const float* __restrict__ w1,
        const float* __restrict__ wes, const float* __restrict__ wop,
        const float* __restrict__ Wf, const float* __restrict__ Wupd,
        const float* __restrict__ Wf2, const float* __restrict__ Wout,
        const float* __restrict__ Wwk, const float* __restrict__ Wws,
        const float* __restrict__ nh, const float* __restrict__ Wg,
        const float* __restrict__ bg) {
    int blk = blockIdx.x;
    int tid = threadIdx.x;

    if (blk < 193) {
        // ---- setup: two 128-thread sub-blocks ----
        int half = tid >> 7, c = tid & 127;
        int ob = blk * 2 + half;   // 0..385
        if (ob < 192) {
            int k = ob;
            float v;
            if (c < 64) { int srcr = (k < 64) ? k : k + 64; v = Wf[srcr * 64 + c]; }
            else v = (k >= 64) ? Wupd[k * 64 + (c - 64)] : 0.f;
            g_Wfu[k * 128 + c] = v;
        } else if (ob < 320) {
            int k = ob - 192;
            float v;
            if (c < 64) v = Wf2[k * 64 + c];
            else v = (k >= 64) ? Wout[(k - 64) * 64 + (c - 64)] : 0.f;
            g_Wb2[k * 128 + c] = v;
        } else if (ob < 384) {
            int k = ob - 320;
            g_Wx[k * 128 + c] = (c < 64) ? Wwk[k * 64 + c] : Wws[k * 64 + (c - 64)];
        } else {
            int b = half;   // blk==192: ob 384/385
            __shared__ float gt[2][64], red[2][64], gtn[2][64];
            int d = c;
            if (d < 64) {
                float acc = bg[d];
                for (int k = 0; k < 64; k++) acc += nh[b * 64 + k] * Wg[k * 64 + d];
                gt[half][d] = acc; red[half][d] = acc * acc;
            }
            __syncthreads();
            if (d == 0) { float s = 0.f; for (int k = 0; k < 64; k++) s += red[half][k]; red[half][0] = s; }
            __syncthreads();
            float nrm = sqrtf(red[half][0]);
            if (d < 64) gtn[half][d] = gt[half][d] / (nrm + 1e-30f);
            __syncthreads();
            if (d < 64) {
                float cf = 0.f, cu = 0.f;
                for (int h = 0; h < 64; h++) {
                    float v = gtn[half][h];
                    cf += v * Wf[(64 + h) * 64 + d];
                    cu += v * Wupd[h * 64 + d];
                }
                g_cF[b * 64 + d] = cf;
                g_cU[b * 64 + d] = cu;
            }
        }
        return;
    }
    if (blk < 321) {
        // ---- opbits ----
        int w = ((blk - 193) * 256 + tid) >> 5;
        int lane = tid & 31;
        int b = w >> 9;
        int rem = w & 511;
        int og = rem >> 7, ng = rem & 127;
        int o = og * 32 + lane;
        const float* wesb = wes + b * NN;
        unsigned word = 0;
        for (int i2 = 0; i2 < 32; i2++) {
            int n = ng * 32 + i2;
            float v = wop[((size_t)(b * NN + n)) * OO + o];
            float s = wesb[n];
            word |= ((v != 0.f && s != 0.f) ? 1u : 0u) << i2;
        }
        g_bits[((b * OO + o) << 7) + ng] = word;
        return;
    }

    // ---- sparse aggregations ----
    __shared__ int buf[8][256];
    int wip = tid >> 5, lane = tid & 31;
    unsigned ltm = (1u << lane) - 1u;
    int* B = buf[wip];
    int ablk = blk - 321;

    if (ablk < 1024) {
        int row = ablk * 8 + wip;
        int b = row >> 12;
        const float4* wwr = (const float4*)(ww + (size_t)row * NN);
        const float* wemr = wem + (size_t)row * NN;
        const float* w0b = w0 + ((size_t)b * LL) * 64;
        const float* w1b = w1 + ((size_t)b * LL) * 64;
        int cnt = 0;
        for (int kk = 0; kk < 32; kk += 8) {
            float4 v[8];
#pragma unroll
            for (int u = 0; u < 8; u++) v[u] = wwr[(size_t)(kk + u) * 32 + lane];
#pragma unroll
            for (int u = 0; u < 8; u++) {
                int m = (v[u].x != 0.f) | ((v[u].y != 0.f) << 1) |
                        ((v[u].z != 0.f) << 2) | ((v[u].w != 0.f) << 3);
#pragma unroll
                for (int e = 0; e < 4; e++) {
                    unsigned bal = __ballot_sync(0xffffffffu, (m >> e) & 1);
                    int pos = cnt + __popc(bal & ltm);
                    if (((m >> e) & 1) && pos < 256)
                        B[pos] = (kk + u) * 128 + lane * 4 + e;
                    cnt += __popc(bal);
                }
            }
        }
        if (cnt > 256) cnt = 256;
        __syncwarp();
        int cnt2 = 0;
        for (int base = 0; base < cnt; base += 32) {
            int t = base + lane;
            int j = (t < cnt) ? B[t] : -1;
            bool val = (j >= 0) && (wemr[j] != 0.f);
            unsigned bal = __ballot_sync(0xffffffffu, val);
            __syncwarp();
            if (val) B[cnt2 + __popc(bal & ltm)] = j;
            cnt2 += __popc(bal);
        }
        __syncwarp();
        float a0 = 0.f, a1 = 0.f, c0 = 0.f, c1 = 0.f;
        int t = 0;
        for (; t + 8 <= cnt2; t += 8) {
            const float* p[8];
#pragma unroll
            for (int q = 0; q < 8; q++) {
                int j = B[t + q];
                p[q] = (j < LL) ? w0b + (size_t)j * 64 : w1b + (size_t)(j - LL) * 64;
            }
            float x[8], y[8];
#pragma unroll
            for (int q = 0; q < 8; q++) { x[q] = p[q][lane]; y[q] = p[q][lane + 32]; }
#pragma unroll
            for (int q = 0; q < 8; q++) {
                if (q & 1) { c0 += x[q]; c1 += y[q]; } else { a0 += x[q]; a1 += y[q]; }
            }
        }
        for (; t < cnt2; t++) {
            int j = B[t];
            const float* p = (j < LL) ? w0b + (size_t)j * 64 : w1b + (size_t)(j - LL) * 64;
            a0 += p[lane]; a1 += p[lane + 32];
        }
        a0 += c0; a1 += c1;
        float inv = 1.f / ((float)cnt2 + 1e-30f);
        g_aggK[(size_t)row * 64 + lane] = a0 * inv;
        g_aggK[(size_t)row * 64 + lane + 32] = a1 * inv;
        if (lane == 0) g_gateK[row] = (cnt2 > 0) ? 1.f : 0.f;
    } else {
        int row = (ablk - 1024) * 8 + wip;
        int b = row >> 12;
        int i = row & (NN - 1);
        const float* mat;
        const float* Xb;
        if (i < LL) {
            mat = dp0 + ((size_t)(b * LL + i)) * LL;
            Xb = w0 + ((size_t)b * LL) * 64;
        } else {
            mat = dp1 + ((size_t)(b * LL + i - LL)) * LL;
            Xb = w1 + ((size_t)b * LL) * 64;
        }
        const float4* m4 = (const float4*)mat;
        int cnt = 0;
        for (int kk = 0; kk < 16; kk += 8) {
            float4 v[8];
#pragma unroll
            for (int u = 0; u < 8; u++) v[u] = m4[(size_t)(kk + u) * 32 + lane];
#pragma unroll
            for (int u = 0; u < 8; u++) {
                int m = (v[u].x != 0.f) | ((v[u].y != 0.f) << 1) |
                        ((v[u].z != 0.f) << 2) | ((v[u].w != 0.f) << 3);
#pragma unroll
                for (int e = 0; e < 4; e++) {
                    unsigned bal = __ballot_sync(0xffffffffu, (m >> e) & 1);
                    int pos = cnt + __popc(bal & ltm);
                    if (((m >> e) & 1) && pos < 256)
                        B[pos] = (kk + u) * 128 + lane * 4 + e;
                    cnt += __popc(bal);
                }
            }
        }
        if (cnt > 256) cnt = 256;
        __syncwarp();
        float a0 = 0.f, a1 = 0.f, c0 = 0.f, c1 = 0.f;
        int t = 0;
        for (; t + 8 <= cnt; t += 8) {
            const float* p[8];
#pragma unroll
            for (int q = 0; q < 8; q++) p[q] = Xb + (size_t)B[t + q] * 64;
            float x[8], y[8];
#pragma unroll
            for (int q = 0; q < 8; q++) { x[q] = p[q][lane]; y[q] = p[q][lane + 32]; }
#pragma unroll
            for (int q = 0; q < 8; q++) {
                if (q & 1) { c0 += x[q]; c1 += y[q]; } else { a0 += x[q]; a1 += y[q]; }
            }
        }
        for (; t < cnt; t++) {
            const float* p = Xb + (size_t)B[t] * 64;
            a0 += p[lane]; a1 += p[lane + 32];
        }
        a0 += c0; a1 += c1;
        float inv = 1.f / ((float)cnt + 1e-30f);
        g_aggS[(size_t)row * 64 + lane] = a0 * inv;
        g_aggS[(size_t)row * 64 + lane + 32] = a1 * inv;
        if (lane == 0) g_gateS[row] = (cnt > 0) ? 1.f : 0.f;
    }
}

// ================= fused mega-GEMM: 128 threads, 4 rows/thread =================
__global__ void __launch_bounds__(128) k_fu(const float* __restrict__ w0,
                                            const float* __restrict__ w1,
                                            const float* __restrict__ gw,
                                            const float* __restrict__ bwk,
                                            const float* __restrict__ bws,
                                            const float* __restrict__ bf,
                                            const float* __restrict__ bupd,
                                            const float* __restrict__ Wo,
                                            const float* __restrict__ bo,
                                            float* __restrict__ out) {
    __shared__ float SM[2176 + 2176 + 6272];
    float* R1 = SM;            // aggK (A) / allw (B) / -, stride 68
    float* R2 = SM + 2176;     // aggS (A) / upd (B-epi,C), stride 68
    float* WREG = SM + 4352;   // WcS 16x128 (A,B); phase C: Wo stride 68
    float* C2 = WREG + 2048;   // 32 x stride 132 (written epi-A, read B)

    int tid = threadIdx.x;
    int tx = tid & 15, ty = tid >> 4;   // ty 0..7
    int r0 = blockIdx.x * 32;
    int b = r0 >> 12, i0 = r0 & (NN - 1);

    // load aggK / aggS tiles
    {
        int row = tid >> 2, colq = (tid & 3) * 16;
        const float* sK = g_aggK + (size_t)(r0 + row) * 64 + colq;
        const float* sS = g_aggS + (size_t)(r0 + row) * 64 + colq;
#pragma unroll
        for (int u = 0; u < 4; u++) {
            *(float4*)&R1[row * 68 + colq + u * 4] = *(const float4*)(sK + u * 4);
            *(float4*)&R2[row * 68 + colq + u * 4] = *(const float4*)(sS + u * 4);
        }
    }

    ull acc[4][4];
#pragma unroll
    for (int i = 0; i < 4; i++)
#pragma unroll
        for (int j = 0; j < 4; j++) acc[i][j] = 0ull;

    // ---- phase A: [aggK|aggS] @ [Wwk|Wws] ----
    for (int kt = 0; kt < 64; kt += 16) {
        __syncthreads();
        {
            int row = tid >> 3, col = (tid & 7) * 16;
#pragma unroll
            for (int u = 0; u < 4; u++)
                *(float4*)&WREG[row * 128 + col + u * 4] =
                    *(const float4*)(g_Wx + (kt + row) * 128 + col + u * 4);
        }
        __syncthreads();
#pragma unroll
        for (int k = 0; k < 16; k++) {
            ulonglong2 p0 = *(const ulonglong2*)&WREG[k * 128 + tx * 4];
            ulonglong2 p1 = *(const ulonglong2*)&WREG[k * 128 + 64 + tx * 4];
#pragma unroll
            for (int i = 0; i < 4; i++) {
                int r = ty * 4 + i;
                ull ak = dup2(R1[r * 68 + kt + k]);
                ull as = dup2(R2[r * 68 + kt + k]);
                ffma2(acc[i][0], ak, p0.x);
                ffma2(acc[i][1], ak, p0.y);
                ffma2(acc[i][2], as, p1.x);
                ffma2(acc[i][3], as, p1.y);
            }
        }
    }
    // epilogue A: bias-gate + l2n -> C2
#pragma unroll
    for (int i = 0; i < 4; i++) {
        int r = ty * 4 + i;
        float gk = g_gateK[r0 + r], gs = g_gateS[r0 + r];
        float wk[4], ws[4];
#pragma unroll
        for (int j = 0; j < 2; j++) {
            float2 pk = up2(acc[i][j]);
            float2 ps = up2(acc[i][2 + j]);
            int c = tx * 4 + 2 * j;
            wk[2 * j] = pk.x + gk * bwk[c];
            wk[2 * j + 1] = pk.y + gk * bwk[c + 1];
            ws[2 * j] = ps.x + gs * bws[c];
            ws[2 * j + 1] = ps.y + gs * bws[c + 1];
        }
        float sk = 0.f, ss = 0.f;
#pragma unroll
        for (int q = 0; q < 4; q++) { sk += wk[q] * wk[q]; ss += ws[q] * ws[q]; }
#pragma unroll
        for (int d = 8; d; d >>= 1) {
            sk += __shfl_xor_sync(0xffffffffu, sk, d);
            ss += __shfl_xor_sync(0xffffffffu, ss, d);
        }
        float ik = 1.f / (sqrtf(sk) + 1e-30f);
        float is = 1.f / (sqrtf(ss) + 1e-30f);
        *(float4*)&C2[r * 132 + tx * 4] =
            make_float4(wk[0] * ik, wk[1] * ik, wk[2] * ik, wk[3] * ik);
        *(float4*)&C2[r * 132 + 64 + tx * 4] =
            make_float4(ws[0] * is, ws[1] * is, ws[2] * is, ws[3] * is);
    }
    __syncthreads();
    // load allw into R1
    {
        int row = tid >> 2, colq = (tid & 3) * 16;
        int i = i0 + row;
        const float* src = (i < LL) ? (w0 + ((size_t)(b * LL + i)) * 64)
                                    : (w1 + ((size_t)(b * LL + i - LL)) * 64);
#pragma unroll
        for (int u = 0; u < 4; u++)
            *(float4*)&R1[row * 68 + colq + u * 4] = *(const float4*)(src + colq + u * 4);
    }
#pragma unroll
    for (int i = 0; i < 4; i++)
#pragma unroll
        for (int j = 0; j < 4; j++) acc[i][j] = 0ull;

    // ---- phase B: [allw|wk|ws] @ Wfu ----
    for (int kt = 0; kt < 192; kt += 16) {
        __syncthreads();
        {
            int row = tid >> 3, col = (tid & 7) * 16;
#pragma unroll
            for (int u = 0; u < 4; u++)
                *(float4*)&WREG[row * 128 + col + u * 4] =
                    *(const float4*)(g_Wfu + (kt + row) * 128 + col + u * 4);
        }
        __syncthreads();
        const float* arow[4];
#pragma unroll
        for (int i = 0; i < 4; i++) {
            int r = ty * 4 + i;
            arow[i] = (kt < 64) ? &R1[r * 68 + kt] : &C2[r * 132 + kt - 64];
        }
#pragma unroll
        for (int k = 0; k < 16; k++) {
            ulonglong2 p0 = *(const ulonglong2*)&WREG[k * 128 + tx * 4];
            ulonglong2 p1 = *(const ulonglong2*)&WREG[k * 128 + 64 + tx * 4];
#pragma unroll
            for (int i = 0; i < 4; i++) {
                ull a = dup2(arow[i][k]);
                ffma2(acc[i][0], a, p0.x);
                ffma2(acc[i][1], a, p0.y);
                ffma2(acc[i][2], a, p1.x);
                ffma2(acc[i][3], a, p1.y);
            }
        }
    }
    __syncthreads();
    // epilogue B: gates + update -> out + R2
#pragma unroll
    for (int i = 0; i < 4; i++) {
        int r = ty * 4 + i;
        int iw = i0 + r;
        float gate = (gw[b * NN + iw] > 0.f) ? 1.f : 0.f;
        float4 aw4 = *(const float4*)&R1[r * 68 + tx * 4];
        float aw[4] = {aw4.x, aw4.y, aw4.z, aw4.w};
        float o[4];
#pragma unroll
        for (int j = 0; j < 2; j++) {
            float2 pf = up2(acc[i][j]);
            float2 pu = up2(acc[i][2 + j]);
#pragma unroll
            for (int h = 0; h < 2; h++) {
                int c = tx * 4 + 2 * j + h;
                float fv = sigm((h ? pf.y : pf.x) + bf[c] + gate * g_cF[b * 64 + c]);
                float uv = fmaxf((h ? pu.y : pu.x) + bupd[c] + gate * g_cU[b * 64 + c], 0.f);
                o[2 * j + h] = fmaxf(fv, FTVAL) * aw[2 * j + h] + (1.f - fv) * uv;
            }
        }
        *(float4*)(out + ((size_t)(b * NOUT + iw)) * 64 + tx * 4) =
            make_float4(o[0], o[1], o[2], o[3]);
        *(float4*)&R2[r * 68 + tx * 4] = make_float4(o[0], o[1], o[2], o[3]);
    }
    __syncthreads();
    // ---- phase C: Y = upd @ Wo + bo ----
    {
        int row = tid >> 1, colq = (tid & 1) * 32;
#pragma unroll
        for (int u = 0; u < 8; u++)
            *(float4*)&WREG[row * 68 + colq + u * 4] =
                *(const float4*)(Wo + row * 64 + colq + u * 4);
    }
    __syncthreads();
    ull acc2[4][2];
#pragma unroll
    for (int i = 0; i < 4; i++) { acc2[i][0] = 0ull; acc2[i][1] = 0ull; }
#pragma unroll
    for (int k = 0; k < 64; k++) {
        ulonglong2 wp = *(const ulonglong2*)&WREG[k * 68 + tx * 4];
#pragma unroll
        for (int i = 0; i < 4; i++) {
            ull a = dup2(R2[(ty * 4 + i) * 68 + k]);
            ffma2(acc2[i][0], a, wp.x);
            ffma2(acc2[i][1], a, wp.y);
        }
    }
#pragma unroll
    for (int i = 0; i < 4; i++) {
        int rg = r0 + ty * 4 + i;
        int c = tx * 4;
        float2 p0 = up2(acc2[i][0]), p1 = up2(acc2[i][1]);
        *(float4*)(g_Y + (size_t)rg * 64 + c) =
            make_float4(p0.x + bo[c], p0.y + bo[c + 1], p1.x + bo[c + 2], p1.y + bo[c + 3]);
    }
}

// ---------------- op aggregation ----------------
__global__ void __launch_bounds__(256) k_agg_op2(const float* __restrict__ opE) {
    int rg = blockIdx.x;
    int b = rg >> 7;
    int tid = threadIdx.x, d = tid & 63, grp = tid >> 6;
    __shared__ float part[4][65];
    __shared__ int sdeg[4];
    const float* Yb = g_Y + (((size_t)b) << 12) * 64;
    unsigned base = (unsigned)rg * 128;
    float a = 0.f;
    int cnt = 0;
    for (int wi = grp; wi < 128; wi += 4) {
        unsigned bits = g_bits[base + wi];
        cnt += __popc(bits);
        while (bits) {
            int j = wi * 32 + (__ffs(bits) - 1);
            bits &= bits - 1u;
            a += Yb[(size_t)j * 64 + d];
        }
    }
    part[grp][d] = a;
    if (d == 0) sdeg[grp] = cnt;
    __syncthreads();
    if (tid < 64) {
        float s = part[0][tid] + part[1][tid] + part[2][tid] + part[3][tid];
        int deg = sdeg[0] + sdeg[1] + sdeg[2] + sdeg[3];
        g_cat2[(size_t)rg * 128 + 64 + tid] = s / ((float)deg + 1e-30f);
        g_cat2[(size_t)rg * 128 + tid] = opE[(size_t)rg * 64 + tid];
    }
}

// ---------------- op final ----------------
__global__ void __launch_bounds__(256) k_opfinal(const float* __restrict__ opE,
                                                 const float* __restrict__ bf2,
                                                 const float* __restrict__ bout,
                                                 float* __restrict__ out) {
    __shared__ float Asm[32 * 132];
    __shared__ float WcS[16 * 128];
    int tid = threadIdx.x, tx = tid & 15, ty = tid >> 4;
    int r0 = blockIdx.x * 32;
    {
        int row = tid >> 3, col = (tid & 7) * 16;
#pragma unroll
        for (int u = 0; u < 4; u++)
            *(float4*)&Asm[row * 132 + col + u * 4] =
                *(const float4*)(g_cat2 + (size_t)(r0 + row) * 128 + col + u * 4);
    }
    ull acc[2][4];
#pragma unroll
    for (int i = 0; i < 2; i++)
#pragma unroll
        for (int j = 0; j < 4; j++) acc[i][j] = 0ull;
    for (int kt = 0; kt < 128; kt += 16) {
        __syncthreads();
        {
            int row = tid >> 4, col = (tid & 15) * 8;
            *(float4*)&WcS[row * 128 + col] = *(const float4*)(g_Wb2 + (kt + row) * 128 + col);
            *(float4*)&WcS[row * 128 + col + 4] = *(const float4*)(g_Wb2 + (kt + row) * 128 + col + 4);
        }
        __syncthreads();
#pragma unroll
        for (int k = 0; k < 16; k++) {
            ulonglong2 p0 = *(const ulonglong2*)&WcS[k * 128 + tx * 4];
            ulonglong2 p1 = *(const ulonglong2*)&WcS[k * 128 + 64 + tx * 4];
#pragma unroll
            for (int i = 0; i < 2; i++) {
                ull a = dup2(Asm[(ty * 2 + i) * 132 + kt + k]);
                ffma2(acc[i][0], a, p0.x);
                ffma2(acc[i][1], a, p0.y);
                ffma2(acc[i][2], a, p1.x);
                ffma2(acc[i][3], a, p1.y);
            }
        }
    }
#pragma unroll
    for (int i = 0; i < 2; i++) {
        int rg = r0 + ty * 2 + i;
        int bq = rg >> 7, oo = rg & (OO - 1);
        float4 e4 = *(const float4*)(opE + (size_t)rg * 64 + tx * 4);
        float ev[4] = {e4.x, e4.y, e4.z, e4.w};
        float o[4];
#pragma unroll
        for (int j = 0; j < 2; j++) {
            float2 pf = up2(acc[i][j]);
            float2 pu = up2(acc[i][2 + j]);
#pragma unroll
            for (int h = 0; h < 2; h++) {
                int c = tx * 4 + 2 * j + h;
                float fv = sigm((h ? pf.y : pf.x) + bf2[c]);
                float uv = fmaxf((h ? pu.y : pu.x) + bout[c], 0.f);
                o[2 * j + h] = fmaxf(fv, FTVAL) * ev[2 * j + h] + (1.f - fv) * uv;
            }
        }
        *(float4*)(out + ((size_t)(bq * NOUT + NN + oo)) * 64 + tx * 4) =
            make_float4(o[0], o[1], o[2], o[3]);
    }
}

// ---------------- launch ----------------
extern "C" void kernel_launch(void* const* d_in, const int* in_sizes, int n_in,
                              void* d_out, int out_size) {
    (void)in_sizes; (void)n_in; (void)out_size;
    const float* w0   = (const float*)d_in[0];
    const float* w1   = (const float*)d_in[1];
    const float* nh   = (const float*)d_in[2];
    const float* opE  = (const float*)d_in[3];
    const float* wes  = (const float*)d_in[4];
    const float* wem  = (const float*)d_in[5];
    const float* wop  = (const float*)d_in[6];
    const float* ww   = (const float*)d_in[7];
    const float* dp0  = (const float*)d_in[8];
    const float* dp1  = (const float*)d_in[9];
    const float* gw   = (const float*)d_in[10];
    const float* Wg   = (const float*)d_in[11];
    const float* bg   = (const float*)d_in[12];
    const float* Wwk  = (const float*)d_in[13];
    const float* bwk  = (const float*)d_in[14];
    const float* Wws  = (const float*)d_in[15];
    const float* bws  = (const float*)d_in[16];
    const float* Wo   = (const float*)d_in[17];
    const float* bo   = (const float*)d_in[18];
    const float* Wupd = (const float*)d_in[19];
    const float* bupd = (const float*)d_in[20];
    const float* Wf   = (const float*)d_in[21];
    const float* bf   = (const float*)d_in[22];
    const float* Wf2  = (const float*)d_in[23];
    const float* bf2  = (const float*)d_in[24];
    const float* Wout = (const float*)d_in[25];
    const float* bout = (const float*)d_in[26];
    float* out = (float*)d_out;

    k_mega<<<2369, 256>>>(ww, wem, dp0, dp1, w0, w1, wes, wop,
                          Wf, Wupd, Wf2, Wout, Wwk, Wws, nh, Wg, bg);
    k_fu<<<256, 128>>>(w0, w1, gw, bwk, bws, bf, bupd, Wo, bo, out);
    k_agg_op2<<<256, 256>>>(opE);
    k_opfinal<<<8, 256>>>(opE, bf2, bout, out);
}

// round 8
// speedup vs baseline: 2.7397x; 1.1077x over previous
#include <cuda_runtime.h>
#include <math.h>

#define LL 2048
#define NN 4096
#define OO 128
#define NOUT 4224
#define FTVAL 0.2f

typedef unsigned long long ull;

// ---------------- scratch ----------------
static __device__ float g_aggK[(size_t)2 * NN * 64];
static __device__ float g_aggS[(size_t)2 * NN * 64];
static __device__ float g_gateK[2 * NN];
static __device__ float g_gateS[2 * NN];
static __device__ float g_Y[(size_t)2 * NN * 64];
static __device__ float g_Wx[64 * 128];     // [Wwk | Wws]
static __device__ float g_Wfu[192 * 128];   // [WfR | WuR]
static __device__ float g_Wb2[128 * 128];   // [Wf2 | Wout(pad)]
static __device__ float g_cF[2 * 64];
static __device__ float g_cU[2 * 64];
static __device__ unsigned g_bits[2 * OO * 128];

// ---------------- helpers ----------------
__device__ __forceinline__ ull dup2(float a) {
    ull d; asm("mov.b64 %0, {%1, %1};" : "=l"(d) : "f"(a)); return d;
}
__device__ __forceinline__ void ffma2(ull &c, ull a, ull b) {
    asm("fma.rn.f32x2 %0, %1, %2, %3;" : "=l"(c) : "l"(a), "l"(b), "l"(c));
}
__device__ __forceinline__ float2 up2(ull v) {
    float2 f; asm("mov.b64 {%0, %1}, %2;" : "=f"(f.x), "=f"(f.y) : "l"(v)); return f;
}
__device__ __forceinline__ float sigm(float x) { return 1.f / (1.f + __expf(-x)); }

// ================= mega kernel: setup (193) + opbits (128) + agg (2048) =================
__global__ void __launch_bounds__(256) k_mega(
        const float* __restrict__ ww, const float* __restrict__ wem,
        const float* __restrict__ dp0, const float* __restrict__ dp1,
        const float* __restrict__ w0, const float* __restrict__ w1,
        const float* __restrict__ wes, const float* __restrict__ wop,
        const float* __restrict__ Wf, const float* __restrict__ Wupd,
        const float* __restrict__ Wf2, const float* __restrict__ Wout,
        const float* __restrict__ Wwk, const float* __restrict__ Wws,
        const float* __restrict__ nh, const float* __restrict__ Wg,
        const float* __restrict__ bg) {
    int blk = blockIdx.x;
    int tid = threadIdx.x;

    if (blk < 193) {
        int half = tid >> 7, c = tid & 127;
        int ob = blk * 2 + half;   // 0..385
        if (ob < 192) {
            int k = ob;
            float v;
            if (c < 64) { int srcr = (k < 64) ? k : k + 64; v = Wf[srcr * 64 + c]; }
            else v = (k >= 64) ? Wupd[k * 64 + (c - 64)] : 0.f;
            g_Wfu[k * 128 + c] = v;
        } else if (ob < 320) {
            int k = ob - 192;
            float v;
            if (c < 64) v = Wf2[k * 64 + c];
            else v = (k >= 64) ? Wout[(k - 64) * 64 + (c - 64)] : 0.f;
            g_Wb2[k * 128 + c] = v;
        } else if (ob < 384) {
            int k = ob - 320;
            g_Wx[k * 128 + c] = (c < 64) ? Wwk[k * 64 + c] : Wws[k * 64 + (c - 64)];
        } else {
            int b = half;
            __shared__ float gt[2][64], red[2][64], gtn[2][64];
            int d = c;
            if (d < 64) {
                float acc = bg[d];
                for (int k = 0; k < 64; k++) acc += nh[b * 64 + k] * Wg[k * 64 + d];
                gt[half][d] = acc; red[half][d] = acc * acc;
            }
            __syncthreads();
            if (d == 0) { float s = 0.f; for (int k = 0; k < 64; k++) s += red[half][k]; red[half][0] = s; }
            __syncthreads();
            float nrm = sqrtf(red[half][0]);
            if (d < 64) gtn[half][d] = gt[half][d] / (nrm + 1e-30f);
            __syncthreads();
            if (d < 64) {
                float cf = 0.f, cu = 0.f;
                for (int h = 0; h < 64; h++) {
                    float v = gtn[half][h];
                    cf += v * Wf[(64 + h) * 64 + d];
                    cu += v * Wupd[h * 64 + d];
                }
                g_cF[b * 64 + d] = cf;
                g_cU[b * 64 + d] = cu;
            }
        }
        return;
    }
    if (blk < 321) {
        int w = ((blk - 193) * 256 + tid) >> 5;
        int lane = tid & 31;
        int b = w >> 9;
        int rem = w & 511;
        int og = rem >> 7, ng = rem & 127;
        int o = og * 32 + lane;
        const float* wesb = wes + b * NN;
        unsigned word = 0;
        for (int i2 = 0; i2 < 32; i2++) {
            int n = ng * 32 + i2;
            float v = wop[((size_t)(b * NN + n)) * OO + o];
            float s = wesb[n];
            word |= ((v != 0.f && s != 0.f) ? 1u : 0u) << i2;
        }
        g_bits[((b * OO + o) << 7) + ng] = word;
        return;
    }

    // ---- sparse aggregations ----
    __shared__ int buf[8][256];
    int wip = tid >> 5, lane = tid & 31;
    unsigned ltm = (1u << lane) - 1u;
    int* B = buf[wip];
    int ablk = blk - 321;

    if (ablk < 1024) {
        int row = ablk * 8 + wip;
        int b = row >> 12;
        const float4* wwr = (const float4*)(ww + (size_t)row * NN);
        const float* wemr = wem + (size_t)row * NN;
        const float* w0b = w0 + ((size_t)b * LL) * 64;
        const float* w1b = w1 + ((size_t)b * LL) * 64;
        int cnt = 0;
        for (int kk = 0; kk < 32; kk += 8) {
            float4 v[8];
#pragma unroll
            for (int u = 0; u < 8; u++) v[u] = wwr[(size_t)(kk + u) * 32 + lane];
#pragma unroll
            for (int u = 0; u < 8; u++) {
                int m = (v[u].x != 0.f) | ((v[u].y != 0.f) << 1) |
                        ((v[u].z != 0.f) << 2) | ((v[u].w != 0.f) << 3);
#pragma unroll
                for (int e = 0; e < 4; e++) {
                    unsigned bal = __ballot_sync(0xffffffffu, (m >> e) & 1);
                    int pos = cnt + __popc(bal & ltm);
                    if (((m >> e) & 1) && pos < 256)
                        B[pos] = (kk + u) * 128 + lane * 4 + e;
                    cnt += __popc(bal);
                }
            }
        }
        if (cnt > 256) cnt = 256;
        __syncwarp();
        int cnt2 = 0;
        for (int base = 0; base < cnt; base += 32) {
            int t = base + lane;
            int j = (t < cnt) ? B[t] : -1;
            bool val = (j >= 0) && (wemr[j] != 0.f);
            unsigned bal = __ballot_sync(0xffffffffu, val);
            __syncwarp();
            if (val) B[cnt2 + __popc(bal & ltm)] = j;
            cnt2 += __popc(bal);
        }
        __syncwarp();
        float a0 = 0.f, a1 = 0.f, c0 = 0.f, c1 = 0.f;
        int t = 0;
        for (; t + 8 <= cnt2; t += 8) {
            const float* p[8];
#pragma unroll
            for (int q = 0; q < 8; q++) {
                int j = B[t + q];
                p[q] = (j < LL) ? w0b + (size_t)j * 64 : w1b + (size_t)(j - LL) * 64;
            }
            float x[8], y[8];
#pragma unroll
            for (int q = 0; q < 8; q++) { x[q] = p[q][lane]; y[q] = p[q][lane + 32]; }
#pragma unroll
            for (int q = 0; q < 8; q++) {
                if (q & 1) { c0 += x[q]; c1 += y[q]; } else { a0 += x[q]; a1 += y[q]; }
            }
        }
        for (; t < cnt2; t++) {
            int j = B[t];
            const float* p = (j < LL) ? w0b + (size_t)j * 64 : w1b + (size_t)(j - LL) * 64;
            a0 += p[lane]; a1 += p[lane + 32];
        }
        a0 += c0; a1 += c1;
        float inv = 1.f / ((float)cnt2 + 1e-30f);
        g_aggK[(size_t)row * 64 + lane] = a0 * inv;
        g_aggK[(size_t)row * 64 + lane + 32] = a1 * inv;
        if (lane == 0) g_gateK[row] = (cnt2 > 0) ? 1.f : 0.f;
    } else {
        int row = (ablk - 1024) * 8 + wip;
        int b = row >> 12;
        int i = row & (NN - 1);
        const float* mat;
        const float* Xb;
        if (i < LL) {
            mat = dp0 + ((size_t)(b * LL + i)) * LL;
            Xb = w0 + ((size_t)b * LL) * 64;
        } else {
            mat = dp1 + ((size_t)(b * LL + i - LL)) * LL;
            Xb = w1 + ((size_t)b * LL) * 64;
        }
        const float4* m4 = (const float4*)mat;
        int cnt = 0;
        for (int kk = 0; kk < 16; kk += 8) {
            float4 v[8];
#pragma unroll
            for (int u = 0; u < 8; u++) v[u] = m4[(size_t)(kk + u) * 32 + lane];
#pragma unroll
            for (int u = 0; u < 8; u++) {
                int m = (v[u].x != 0.f) | ((v[u].y != 0.f) << 1) |
                        ((v[u].z != 0.f) << 2) | ((v[u].w != 0.f) << 3);
#pragma unroll
                for (int e = 0; e < 4; e++) {
                    unsigned bal = __ballot_sync(0xffffffffu, (m >> e) & 1);
                    int pos = cnt + __popc(bal & ltm);
                    if (((m >> e) & 1) && pos < 256)
                        B[pos] = (kk + u) * 128 + lane * 4 + e;
                    cnt += __popc(bal);
                }
            }
        }
        if (cnt > 256) cnt = 256;
        __syncwarp();
        float a0 = 0.f, a1 = 0.f, c0 = 0.f, c1 = 0.f;
        int t = 0;
        for (; t + 8 <= cnt; t += 8) {
            const float* p[8];
#pragma unroll
            for (int q = 0; q < 8; q++) p[q] = Xb + (size_t)B[t + q] * 64;
            float x[8], y[8];
#pragma unroll
            for (int q = 0; q < 8; q++) { x[q] = p[q][lane]; y[q] = p[q][lane + 32]; }
#pragma unroll
            for (int q = 0; q < 8; q++) {
                if (q & 1) { c0 += x[q]; c1 += y[q]; } else { a0 += x[q]; a1 += y[q]; }
            }
        }
        for (; t < cnt; t++) {
            const float* p = Xb + (size_t)B[t] * 64;
            a0 += p[lane]; a1 += p[lane + 32];
        }
        a0 += c0; a1 += c1;
        float inv = 1.f / ((float)cnt + 1e-30f);
        g_aggS[(size_t)row * 64 + lane] = a0 * inv;
        g_aggS[(size_t)row * 64 + lane + 32] = a1 * inv;
        if (lane == 0) g_gateS[row] = (cnt > 0) ? 1.f : 0.f;
    }
}

// ================= fused mega-GEMM: 128 threads, 4 rows/thread =================
__global__ void __launch_bounds__(128) k_fu(const float* __restrict__ w0,
                                            const float* __restrict__ w1,
                                            const float* __restrict__ gw,
                                            const float* __restrict__ bwk,
                                            const float* __restrict__ bws,
                                            const float* __restrict__ bf,
                                            const float* __restrict__ bupd,
                                            const float* __restrict__ Wo,
                                            const float* __restrict__ bo,
                                            float* __restrict__ out) {
    __shared__ float SM[2176 + 2176 + 6272];
    float* R1 = SM;            // aggK (A) / allw (B), stride 68
    float* R2 = SM + 2176;     // aggS (A) / upd (B-epi,C), stride 68
    float* WREG = SM + 4352;   // weight chunk 16x128; phase C: Wo stride 68
    float* C2 = WREG + 2048;   // 32 x stride 132

    int tid = threadIdx.x;
    int tx = tid & 15, ty = tid >> 4;
    int r0 = blockIdx.x * 32;
    int b = r0 >> 12, i0 = r0 & (NN - 1);

    {
        int row = tid >> 2, colq = (tid & 3) * 16;
        const float* sK = g_aggK + (size_t)(r0 + row) * 64 + colq;
        const float* sS = g_aggS + (size_t)(r0 + row) * 64 + colq;
#pragma unroll
        for (int u = 0; u < 4; u++) {
            *(float4*)&R1[row * 68 + colq + u * 4] = *(const float4*)(sK + u * 4);
            *(float4*)&R2[row * 68 + colq + u * 4] = *(const float4*)(sS + u * 4);
        }
    }

    ull acc[4][4];
#pragma unroll
    for (int i = 0; i < 4; i++)
#pragma unroll
        for (int j = 0; j < 4; j++) acc[i][j] = 0ull;

    // ---- phase A: [aggK|aggS] @ [Wwk|Wws] ----
    for (int kt = 0; kt < 64; kt += 16) {
        __syncthreads();
        {
            int row = tid >> 3, col = (tid & 7) * 16;
#pragma unroll
            for (int u = 0; u < 4; u++)
                *(float4*)&WREG[row * 128 + col + u * 4] =
                    *(const float4*)(g_Wx + (kt + row) * 128 + col + u * 4);
        }
        __syncthreads();
#pragma unroll
        for (int k = 0; k < 16; k++) {
            ulonglong2 p0 = *(const ulonglong2*)&WREG[k * 128 + tx * 4];
            ulonglong2 p1 = *(const ulonglong2*)&WREG[k * 128 + 64 + tx * 4];
#pragma unroll
            for (int i = 0; i < 4; i++) {
                int r = ty * 4 + i;
                ull ak = dup2(R1[r * 68 + kt + k]);
                ull as = dup2(R2[r * 68 + kt + k]);
                ffma2(acc[i][0], ak, p0.x);
                ffma2(acc[i][1], ak, p0.y);
                ffma2(acc[i][2], as, p1.x);
                ffma2(acc[i][3], as, p1.y);
            }
        }
    }
#pragma unroll
    for (int i = 0; i < 4; i++) {
        int r = ty * 4 + i;
        float gk = g_gateK[r0 + r], gs = g_gateS[r0 + r];
        float wk[4], ws[4];
#pragma unroll
        for (int j = 0; j < 2; j++) {
            float2 pk = up2(acc[i][j]);
            float2 ps = up2(acc[i][2 + j]);
            int c = tx * 4 + 2 * j;
            wk[2 * j] = pk.x + gk * bwk[c];
            wk[2 * j + 1] = pk.y + gk * bwk[c + 1];
            ws[2 * j] = ps.x + gs * bws[c];
            ws[2 * j + 1] = ps.y + gs * bws[c + 1];
        }
        float sk = 0.f, ss = 0.f;
#pragma unroll
        for (int q = 0; q < 4; q++) { sk += wk[q] * wk[q]; ss += ws[q] * ws[q]; }
#pragma unroll
        for (int d = 8; d; d >>= 1) {
            sk += __shfl_xor_sync(0xffffffffu, sk, d);
            ss += __shfl_xor_sync(0xffffffffu, ss, d);
        }
        float ik = 1.f / (sqrtf(sk) + 1e-30f);
        float is = 1.f / (sqrtf(ss) + 1e-30f);
        *(float4*)&C2[r * 132 + tx * 4] =
            make_float4(wk[0] * ik, wk[1] * ik, wk[2] * ik, wk[3] * ik);
        *(float4*)&C2[r * 132 + 64 + tx * 4] =
            make_float4(ws[0] * is, ws[1] * is, ws[2] * is, ws[3] * is);
    }
    __syncthreads();
    {
        int row = tid >> 2, colq = (tid & 3) * 16;
        int i = i0 + row;
        const float* src = (i < LL) ? (w0 + ((size_t)(b * LL + i)) * 64)
                                    : (w1 + ((size_t)(b * LL + i - LL)) * 64);
#pragma unroll
        for (int u = 0; u < 4; u++)
            *(float4*)&R1[row * 68 + colq + u * 4] = *(const float4*)(src + colq + u * 4);
    }
#pragma unroll
    for (int i = 0; i < 4; i++)
#pragma unroll
        for (int j = 0; j < 4; j++) acc[i][j] = 0ull;

    // ---- phase B: [allw|wk|ws] @ Wfu ----
    for (int kt = 0; kt < 192; kt += 16) {
        __syncthreads();
        {
            int row = tid >> 3, col = (tid & 7) * 16;
#pragma unroll
            for (int u = 0; u < 4; u++)
                *(float4*)&WREG[row * 128 + col + u * 4] =
                    *(const float4*)(g_Wfu + (kt + row) * 128 + col + u * 4);
        }
        __syncthreads();
        const float* arow[4];
#pragma unroll
        for (int i = 0; i < 4; i++) {
            int r = ty * 4 + i;
            arow[i] = (kt < 64) ? &R1[r * 68 + kt] : &C2[r * 132 + kt - 64];
        }
#pragma unroll
        for (int k = 0; k < 16; k++) {
            ulonglong2 p0 = *(const ulonglong2*)&WREG[k * 128 + tx * 4];
            ulonglong2 p1 = *(const ulonglong2*)&WREG[k * 128 + 64 + tx * 4];
#pragma unroll
            for (int i = 0; i < 4; i++) {
                ull a = dup2(arow[i][k]);
                ffma2(acc[i][0], a, p0.x);
                ffma2(acc[i][1], a, p0.y);
                ffma2(acc[i][2], a, p1.x);
                ffma2(acc[i][3], a, p1.y);
            }
        }
    }
    __syncthreads();
#pragma unroll
    for (int i = 0; i < 4; i++) {
        int r = ty * 4 + i;
        int iw = i0 + r;
        float gate = (gw[b * NN + iw] > 0.f) ? 1.f : 0.f;
        float4 aw4 = *(const float4*)&R1[r * 68 + tx * 4];
        float aw[4] = {aw4.x, aw4.y, aw4.z, aw4.w};
        float o[4];
#pragma unroll
        for (int j = 0; j < 2; j++) {
            float2 pf = up2(acc[i][j]);
            float2 pu = up2(acc[i][2 + j]);
#pragma unroll
            for (int h = 0; h < 2; h++) {
                int c = tx * 4 + 2 * j + h;
                float fv = sigm((h ? pf.y : pf.x) + bf[c] + gate * g_cF[b * 64 + c]);
                float uv = fmaxf((h ? pu.y : pu.x) + bupd[c] + gate * g_cU[b * 64 + c], 0.f);
                o[2 * j + h] = fmaxf(fv, FTVAL) * aw[2 * j + h] + (1.f - fv) * uv;
            }
        }
        *(float4*)(out + ((size_t)(b * NOUT + iw)) * 64 + tx * 4) =
            make_float4(o[0], o[1], o[2], o[3]);
        *(float4*)&R2[r * 68 + tx * 4] = make_float4(o[0], o[1], o[2], o[3]);
    }
    __syncthreads();
    // ---- phase C: Y = upd @ Wo + bo ----
    {
        int row = tid >> 1, colq = (tid & 1) * 32;
#pragma unroll
        for (int u = 0; u < 8; u++)
            *(float4*)&WREG[row * 68 + colq + u * 4] =
                *(const float4*)(Wo + row * 64 + colq + u * 4);
    }
    __syncthreads();
    ull acc2[4][2];
#pragma unroll
    for (int i = 0; i < 4; i++) { acc2[i][0] = 0ull; acc2[i][1] = 0ull; }
#pragma unroll
    for (int k = 0; k < 64; k++) {
        ulonglong2 wp = *(const ulonglong2*)&WREG[k * 68 + tx * 4];
#pragma unroll
        for (int i = 0; i < 4; i++) {
            ull a = dup2(R2[(ty * 4 + i) * 68 + k]);
            ffma2(acc2[i][0], a, wp.x);
            ffma2(acc2[i][1], a, wp.y);
        }
    }
#pragma unroll
    for (int i = 0; i < 4; i++) {
        int rg = r0 + ty * 4 + i;
        int c = tx * 4;
        float2 p0 = up2(acc2[i][0]), p1 = up2(acc2[i][1]);
        *(float4*)(g_Y + (size_t)rg * 64 + c) =
            make_float4(p0.x + bo[c], p0.y + bo[c + 1], p1.x + bo[c + 2], p1.y + bo[c + 3]);
    }
}

// ================= fused op: aggregate Y + matvec + gates =================
__global__ void __launch_bounds__(256) k_op(const float* __restrict__ opE,
                                            const float* __restrict__ bf2,
                                            const float* __restrict__ bout,
                                            float* __restrict__ out) {
    int rg = blockIdx.x;              // b*128 + o
    int b = rg >> 7, oo = rg & (OO - 1);
    int tid = threadIdx.x;
    __shared__ float part[4][65];
    __shared__ int sdeg[4];
    __shared__ float cat[128];        // [opE row | word_op row]
    __shared__ float vsum[2][128];

    // phase 1: aggregate Y rows by bitmask
    {
        int d = tid & 63, grp = tid >> 6;
        const float* Yb = g_Y + (((size_t)b) << 12) * 64;
        unsigned base = (unsigned)rg * 128;
        float a = 0.f;
        int cnt = 0;
        for (int wi = grp; wi < 128; wi += 4) {
            unsigned bits = g_bits[base + wi];
            cnt += __popc(bits);
            while (bits) {
                int j = wi * 32 + (__ffs(bits) - 1);
                bits &= bits - 1u;
                a += Yb[(size_t)j * 64 + d];
            }
        }
        part[grp][d] = a;
        if (d == 0) sdeg[grp] = cnt;
    }
    __syncthreads();
    if (tid < 64) {
        float s = part[0][tid] + part[1][tid] + part[2][tid] + part[3][tid];
        int deg = sdeg[0] + sdeg[1] + sdeg[2] + sdeg[3];
        cat[64 + tid] = s / ((float)deg + 1e-30f);
        cat[tid] = opE[(size_t)rg * 64 + tid];
    }
    __syncthreads();
    // phase 2: mat-vec  v[c] = sum_k cat[k] * Wb2[k][c], K split in halves
    {
        int half = tid >> 7, c = tid & 127;
        const float* Wb = g_Wb2 + (size_t)half * 64 * 128 + c;
        float a0 = 0.f, a1 = 0.f, a2 = 0.f, a3 = 0.f;
        const float* cp = cat + half * 64;
#pragma unroll
        for (int k = 0; k < 64; k += 4) {
            a0 += cp[k] * Wb[(size_t)k * 128];
            a1 += cp[k + 1] * Wb[(size_t)(k + 1) * 128];
            a2 += cp[k + 2] * Wb[(size_t)(k + 2) * 128];
            a3 += cp[k + 3] * Wb[(size_t)(k + 3) * 128];
        }
        vsum[half][c] = (a0 + a1) + (a2 + a3);
    }
    __syncthreads();
    // phase 3: gates + output (threads 0..63)
    if (tid < 64) {
        float pf = vsum[0][tid] + vsum[1][tid] + bf2[tid];
        float pu = vsum[0][64 + tid] + vsum[1][64 + tid] + bout[tid];
        float fv = sigm(pf);
        float uv = fmaxf(pu, 0.f);
        float e = cat[tid];
        out[((size_t)(b * NOUT + NN + oo)) * 64 + tid] =
            fmaxf(fv, FTVAL) * e + (1.f - fv) * uv;
    }
}

// ---------------- launch ----------------
extern "C" void kernel_launch(void* const* d_in, const int* in_sizes, int n_in,
                              void* d_out, int out_size) {
    (void)in_sizes; (void)n_in; (void)out_size;
    const float* w0   = (const float*)d_in[0];
    const float* w1   = (const float*)d_in[1];
    const float* nh   = (const float*)d_in[2];
    const float* opE  = (const float*)d_in[3];
    const float* wes  = (const float*)d_in[4];
    const float* wem  = (const float*)d_in[5];
    const float* wop  = (const float*)d_in[6];
    const float* ww   = (const float*)d_in[7];
    const float* dp0  = (const float*)d_in[8];
    const float* dp1  = (const float*)d_in[9];
    const float* gw   = (const float*)d_in[10];
    const float* Wg   = (const float*)d_in[11];
    const float* bg   = (const float*)d_in[12];
    const float* Wwk  = (const float*)d_in[13];
    const float* bwk  = (const float*)d_in[14];
    const float* Wws  = (const float*)d_in[15];
    const float* bws  = (const float*)d_in[16];
    const float* Wo   = (const float*)d_in[17];
    const float* bo   = (const float*)d_in[18];
    const float* Wupd = (const float*)d_in[19];
    const float* bupd = (const float*)d_in[20];
    const float* Wf   = (const float*)d_in[21];
    const float* bf   = (const float*)d_in[22];
    const float* Wf2  = (const float*)d_in[23];
    const float* bf2  = (const float*)d_in[24];
    const float* Wout = (const float*)d_in[25];
    const float* bout = (const float*)d_in[26];
    float* out = (float*)d_out;

    k_mega<<<2369, 256>>>(ww, wem, dp0, dp1, w0, w1, wes, wop,
                          Wf, Wupd, Wf2, Wout, Wwk, Wws, nh, Wg, bg);
    k_fu<<<256, 128>>>(w0, w1, gw, bwk, bws, bf, bupd, Wo, bo, out);
    k_op<<<256, 256>>>(opE, bf2, bout, out);
}

// round 9
// speedup vs baseline: 3.1569x; 1.1523x over previous
#include <cuda_runtime.h>
#include <math.h>

#define LL 2048
#define NN 4096
#define OO 128
#define NOUT 4224
#define FTVAL 0.2f

typedef unsigned long long ull;

// ---------------- scratch ----------------
static __device__ float g_aggK[(size_t)2 * NN * 64];
static __device__ float g_aggS[(size_t)2 * NN * 64];
static __device__ float g_gateK[2 * NN];
static __device__ float g_gateS[2 * NN];
static __device__ float g_Y[(size_t)2 * NN * 64];
static __device__ float g_Wx[64 * 128];     // [Wwk | Wws]
static __device__ float g_Wfu[192 * 128];   // [WfR | WuR]
static __device__ float g_Wb2[128 * 128];   // [Wf2 | Wout(pad)]
static __device__ float g_cF[2 * 64];
static __device__ float g_cU[2 * 64];
static __device__ unsigned g_bits[2 * OO * 128];

// ---------------- helpers ----------------
__device__ __forceinline__ ull dup2(float a) {
    ull d; asm("mov.b64 %0, {%1, %1};" : "=l"(d) : "f"(a)); return d;
}
__device__ __forceinline__ void ffma2(ull &c, ull a, ull b) {
    asm("fma.rn.f32x2 %0, %1, %2, %3;" : "=l"(c) : "l"(a), "l"(b), "l"(c));
}
__device__ __forceinline__ float2 up2(ull v) {
    float2 f; asm("mov.b64 {%0, %1}, %2;" : "=f"(f.x), "=f"(f.y) : "l"(v)); return f;
}
__device__ __forceinline__ float sigm(float x) { return 1.f / (1.f + __expf(-x)); }

// exclusive warp scan; returns exclusive prefix, sets total
__device__ __forceinline__ int wscan_excl(int v, int lane, int &total) {
    int x = v;
#pragma unroll
    for (int d = 1; d < 32; d <<= 1) {
        int y = __shfl_up_sync(0xffffffffu, x, d);
        if (lane >= d) x += y;
    }
    total = __shfl_sync(0xffffffffu, x, 31);
    return x - v;
}

// ================= mega kernel: setup (193) + opbits (128) + agg (2048) =================
__global__ void __launch_bounds__(256) k_mega(
        const float* __restrict__ ww, const float* __restrict__ wem,
        const float* __restrict__ dp0, const float* __restrict__ dp1,
        const float* __restrict__ w0, const float* __restrict__ w1,
        const float* __restrict__ wes, const float* __restrict__ wop,
        const float* __restrict__ Wf, const float* __restrict__ Wupd,
        const float* __restrict__ Wf2, const float* __restrict__ Wout,
        const float* __restrict__ Wwk, const float* __restrict__ Wws,
        const float* __restrict__ nh, const float* __restrict__ Wg,
        const float* __restrict__ bg) {
    int blk = blockIdx.x;
    int tid = threadIdx.x;

    if (blk < 193) {
        int half = tid >> 7, c = tid & 127;
        int ob = blk * 2 + half;   // 0..385
        if (ob < 192) {
            int k = ob;
            float v;
            if (c < 64) { int srcr = (k < 64) ? k : k + 64; v = Wf[srcr * 64 + c]; }
            else v = (k >= 64) ? Wupd[k * 64 + (c - 64)] : 0.f;
            g_Wfu[k * 128 + c] = v;
        } else if (ob < 320) {
            int k = ob - 192;
            float v;
            if (c < 64) v = Wf2[k * 64 + c];
            else v = (k >= 64) ? Wout[(k - 64) * 64 + (c - 64)] : 0.f;
            g_Wb2[k * 128 + c] = v;
        } else if (ob < 384) {
            int k = ob - 320;
            g_Wx[k * 128 + c] = (c < 64) ? Wwk[k * 64 + c] : Wws[k * 64 + (c - 64)];
        } else {
            int b = half;
            __shared__ float gt[2][64], red[2][64], gtn[2][64];
            int d = c;
            if (d < 64) {
                float acc = bg[d];
                for (int k = 0; k < 64; k++) acc += nh[b * 64 + k] * Wg[k * 64 + d];
                gt[half][d] = acc; red[half][d] = acc * acc;
            }
            __syncthreads();
            if (d == 0) { float s = 0.f; for (int k = 0; k < 64; k++) s += red[half][k]; red[half][0] = s; }
            __syncthreads();
            float nrm = sqrtf(red[half][0]);
            if (d < 64) gtn[half][d] = gt[half][d] / (nrm + 1e-30f);
            __syncthreads();
            if (d < 64) {
                float cf = 0.f, cu = 0.f;
                for (int h = 0; h < 64; h++) {
                    float v = gtn[half][h];
                    cf += v * Wf[(64 + h) * 64 + d];
                    cu += v * Wupd[h * 64 + d];
                }
                g_cF[b * 64 + d] = cf;
                g_cU[b * 64 + d] = cu;
            }
        }
        return;
    }
    if (blk < 321) {
        int w = ((blk - 193) * 256 + tid) >> 5;
        int lane = tid & 31;
        int b = w >> 9;
        int rem = w & 511;
        int og = rem >> 7, ng = rem & 127;
        int o = og * 32 + lane;
        const float* wesb = wes + b * NN;
        unsigned word = 0;
        for (int i2 = 0; i2 < 32; i2++) {
            int n = ng * 32 + i2;
            float v = wop[((size_t)(b * NN + n)) * OO + o];
            float s = wesb[n];
            word |= ((v != 0.f && s != 0.f) ? 1u : 0u) << i2;
        }
        g_bits[((b * OO + o) << 7) + ng] = word;
        return;
    }

    // ---- sparse aggregations ----
    __shared__ int buf[8][256];
    int wip = tid >> 5, lane = tid & 31;
    unsigned ltm = (1u << lane) - 1u;
    int* B = buf[wip];
    int ablk = blk - 321;

    if (ablk < 1024) {
        // ---- word_w_k: scan ww (per-lane bitmask decode), filter by wem, gather ----
        int row = ablk * 8 + wip;
        int b = row >> 12;
        const float4* wwr = (const float4*)(ww + (size_t)row * NN);
        const float* wemr = wem + (size_t)row * NN;
        const float* w0b = w0 + ((size_t)b * LL) * 64;
        const float* w1b = w1 + ((size_t)b * LL) * 64;
        int cnt = 0;
        for (int kk = 0; kk < 32; kk += 8) {
            float4 v[8];
#pragma unroll
            for (int u = 0; u < 8; u++) v[u] = wwr[(size_t)(kk + u) * 32 + lane];
            unsigned m32 = 0;
#pragma unroll
            for (int u = 0; u < 8; u++) {
                m32 |= (v[u].x != 0.f ? 1u : 0u) << (4 * u);
                m32 |= (v[u].y != 0.f ? 1u : 0u) << (4 * u + 1);
                m32 |= (v[u].z != 0.f ? 1u : 0u) << (4 * u + 2);
                m32 |= (v[u].w != 0.f ? 1u : 0u) << (4 * u + 3);
            }
            int total;
            int off = wscan_excl(__popc(m32), lane, total);
            int pos = cnt + off;
            while (m32) {
                int bs = __ffs(m32) - 1;
                m32 &= m32 - 1u;
                int j = (kk + (bs >> 2)) * 128 + lane * 4 + (bs & 3);
                if (pos < 256) B[pos] = j;
                pos++;
            }
            cnt += total;
        }
        if (cnt > 256) cnt = 256;
        __syncwarp();
        // filter by wem (lane-parallel gathers, re-compact)
        int cnt2 = 0;
        for (int base = 0; base < cnt; base += 32) {
            int t = base + lane;
            int j = (t < cnt) ? B[t] : -1;
            bool val = (j >= 0) && (wemr[j] != 0.f);
            unsigned bal = __ballot_sync(0xffffffffu, val);
            __syncwarp();
            if (val) B[cnt2 + __popc(bal & ltm)] = j;
            cnt2 += __popc(bal);
        }
        __syncwarp();
        // gather (float2 per lane), 8-way unrolled
        float a0 = 0.f, a1 = 0.f, c0 = 0.f, c1 = 0.f;
        int t = 0;
        for (; t + 8 <= cnt2; t += 8) {
            const float2* p[8];
#pragma unroll
            for (int q = 0; q < 8; q++) {
                int j = B[t + q];
                p[q] = (const float2*)((j < LL) ? w0b + (size_t)j * 64
                                                : w1b + (size_t)(j - LL) * 64);
            }
            float2 g[8];
#pragma unroll
            for (int q = 0; q < 8; q++) g[q] = p[q][lane];
#pragma unroll
            for (int q = 0; q < 8; q++) {
                if (q & 1) { c0 += g[q].x; c1 += g[q].y; } else { a0 += g[q].x; a1 += g[q].y; }
            }
        }
        for (; t < cnt2; t++) {
            int j = B[t];
            const float2* p = (const float2*)((j < LL) ? w0b + (size_t)j * 64
                                                       : w1b + (size_t)(j - LL) * 64);
            float2 g = p[lane];
            a0 += g.x; a1 += g.y;
        }
        a0 += c0; a1 += c1;
        float inv = 1.f / ((float)cnt2 + 1e-30f);
        ((float2*)(g_aggK + (size_t)row * 64))[lane] = make_float2(a0 * inv, a1 * inv);
        if (lane == 0) g_gateK[row] = (cnt2 > 0) ? 1.f : 0.f;
    } else {
        // ---- word_w_s: scan depend (per-lane bitmask decode), gather ----
        int row = (ablk - 1024) * 8 + wip;
        int b = row >> 12;
        int i = row & (NN - 1);
        const float* mat;
        const float* Xb;
        if (i < LL) {
            mat = dp0 + ((size_t)(b * LL + i)) * LL;
            Xb = w0 + ((size_t)b * LL) * 64;
        } else {
            mat = dp1 + ((size_t)(b * LL + i - LL)) * LL;
            Xb = w1 + ((size_t)b * LL) * 64;
        }
        const float4* m4 = (const float4*)mat;
        int cnt = 0;
        for (int kk = 0; kk < 16; kk += 8) {
            float4 v[8];
#pragma unroll
            for (int u = 0; u < 8; u++) v[u] = m4[(size_t)(kk + u) * 32 + lane];
            unsigned m32 = 0;
#pragma unroll
            for (int u = 0; u < 8; u++) {
                m32 |= (v[u].x != 0.f ? 1u : 0u) << (4 * u);
                m32 |= (v[u].y != 0.f ? 1u : 0u) << (4 * u + 1);
                m32 |= (v[u].z != 0.f ? 1u : 0u) << (4 * u + 2);
                m32 |= (v[u].w != 0.f ? 1u : 0u) << (4 * u + 3);
            }
            int total;
            int off = wscan_excl(__popc(m32), lane, total);
            int pos = cnt + off;
            while (m32) {
                int bs = __ffs(m32) - 1;
                m32 &= m32 - 1u;
                int j = (kk + (bs >> 2)) * 128 + lane * 4 + (bs & 3);
                if (pos < 256) B[pos] = j;
                pos++;
            }
            cnt += total;
        }
        if (cnt > 256) cnt = 256;
        __syncwarp();
        float a0 = 0.f, a1 = 0.f, c0 = 0.f, c1 = 0.f;
        int t = 0;
        for (; t + 8 <= cnt; t += 8) {
            const float2* p[8];
#pragma unroll
            for (int q = 0; q < 8; q++) p[q] = (const float2*)(Xb + (size_t)B[t + q] * 64);
            float2 g[8];
#pragma unroll
            for (int q = 0; q < 8; q++) g[q] = p[q][lane];
#pragma unroll
            for (int q = 0; q < 8; q++) {
                if (q & 1) { c0 += g[q].x; c1 += g[q].y; } else { a0 += g[q].x; a1 += g[q].y; }
            }
        }
        for (; t < cnt; t++) {
            float2 g = ((const float2*)(Xb + (size_t)B[t] * 64))[lane];
            a0 += g.x; a1 += g.y;
        }
        a0 += c0; a1 += c1;
        float inv = 1.f / ((float)cnt + 1e-30f);
        ((float2*)(g_aggS + (size_t)row * 64))[lane] = make_float2(a0 * inv, a1 * inv);
        if (lane == 0) g_gateS[row] = (cnt > 0) ? 1.f : 0.f;
    }
}

// ================= fused mega-GEMM: 128 threads, 4 rows/thread =================
__global__ void __launch_bounds__(128) k_fu(const float* __restrict__ w0,
                                            const float* __restrict__ w1,
                                            const float* __restrict__ gw,
                                            const float* __restrict__ bwk,
                                            const float* __restrict__ bws,
                                            const float* __restrict__ bf,
                                            const float* __restrict__ bupd,
                                            const float* __restrict__ Wo,
                                            const float* __restrict__ bo,
                                            float* __restrict__ out) {
    __shared__ float SM[2176 + 2176 + 6272];
    float* R1 = SM;            // aggK (A) / allw (B), stride 68
    float* R2 = SM + 2176;     // aggS (A) / upd (B-epi,C), stride 68
    float* WREG = SM + 4352;   // weight chunk 16x128; phase C: Wo stride 68
    float* C2 = WREG + 2048;   // 32 x stride 132

    int tid = threadIdx.x;
    int tx = tid & 15, ty = tid >> 4;
    int r0 = blockIdx.x * 32;
    int b = r0 >> 12, i0 = r0 & (NN - 1);

    {
        int row = tid >> 2, colq = (tid & 3) * 16;
        const float* sK = g_aggK + (size_t)(r0 + row) * 64 + colq;
        const float* sS = g_aggS + (size_t)(r0 + row) * 64 + colq;
#pragma unroll
        for (int u = 0; u < 4; u++) {
            *(float4*)&R1[row * 68 + colq + u * 4] = *(const float4*)(sK + u * 4);
            *(float4*)&R2[row * 68 + colq + u * 4] = *(const float4*)(sS + u * 4);
        }
    }

    ull acc[4][4];
#pragma unroll
    for (int i = 0; i < 4; i++)
#pragma unroll
        for (int j = 0; j < 4; j++) acc[i][j] = 0ull;

    // ---- phase A: [aggK|aggS] @ [Wwk|Wws] ----
    for (int kt = 0; kt < 64; kt += 16) {
        __syncthreads();
        {
            int row = tid >> 3, col = (tid & 7) * 16;
#pragma unroll
            for (int u = 0; u < 4; u++)
                *(float4*)&WREG[row * 128 + col + u * 4] =
                    *(const float4*)(g_Wx + (kt + row) * 128 + col + u * 4);
        }
        __syncthreads();
#pragma unroll
        for (int k = 0; k < 16; k++) {
            ulonglong2 p0 = *(const ulonglong2*)&WREG[k * 128 + tx * 4];
            ulonglong2 p1 = *(const ulonglong2*)&WREG[k * 128 + 64 + tx * 4];
#pragma unroll
            for (int i = 0; i < 4; i++) {
                int r = ty * 4 + i;
                ull ak = dup2(R1[r * 68 + kt + k]);
                ull as = dup2(R2[r * 68 + kt + k]);
                ffma2(acc[i][0], ak, p0.x);
                ffma2(acc[i][1], ak, p0.y);
                ffma2(acc[i][2], as, p1.x);
                ffma2(acc[i][3], as, p1.y);
            }
        }
    }
#pragma unroll
    for (int i = 0; i < 4; i++) {
        int r = ty * 4 + i;
        float gk = g_gateK[r0 + r], gs = g_gateS[r0 + r];
        float wk[4], ws[4];
#pragma unroll
        for (int j = 0; j < 2; j++) {
            float2 pk = up2(acc[i][j]);
            float2 ps = up2(acc[i][2 + j]);
            int c = tx * 4 + 2 * j;
            wk[2 * j] = pk.x + gk * bwk[c];
            wk[2 * j + 1] = pk.y + gk * bwk[c + 1];
            ws[2 * j] = ps.x + gs * bws[c];
            ws[2 * j + 1] = ps.y + gs * bws[c + 1];
        }
        float sk = 0.f, ss = 0.f;
#pragma unroll
        for (int q = 0; q < 4; q++) { sk += wk[q] * wk[q]; ss += ws[q] * ws[q]; }
#pragma unroll
        for (int d = 8; d; d >>= 1) {
            sk += __shfl_xor_sync(0xffffffffu, sk, d);
            ss += __shfl_xor_sync(0xffffffffu, ss, d);
        }
        float ik = 1.f / (sqrtf(sk) + 1e-30f);
        float is = 1.f / (sqrtf(ss) + 1e-30f);
        *(float4*)&C2[r * 132 + tx * 4] =
            make_float4(wk[0] * ik, wk[1] * ik, wk[2] * ik, wk[3] * ik);
        *(float4*)&C2[r * 132 + 64 + tx * 4] =
            make_float4(ws[0] * is, ws[1] * is, ws[2] * is, ws[3] * is);
    }
    __syncthreads();
    {
        int row = tid >> 2, colq = (tid & 3) * 16;
        int i = i0 + row;
        const float* src = (i < LL) ? (w0 + ((size_t)(b * LL + i)) * 64)
                                    : (w1 + ((size_t)(b * LL + i - LL)) * 64);
#pragma unroll
        for (int u = 0; u < 4; u++)
            *(float4*)&R1[row * 68 + colq + u * 4] = *(const float4*)(src + colq + u * 4);
    }
#pragma unroll
    for (int i = 0; i < 4; i++)
#pragma unroll
        for (int j = 0; j < 4; j++) acc[i][j] = 0ull;

    // ---- phase B: [allw|wk|ws] @ Wfu ----
    for (int kt = 0; kt < 192; kt += 16) {
        __syncthreads();
        {
            int row = tid >> 3, col = (tid & 7) * 16;
#pragma unroll
            for (int u = 0; u < 4; u++)
                *(float4*)&WREG[row * 128 + col + u * 4] =
                    *(const float4*)(g_Wfu + (kt + row) * 128 + col + u * 4);
        }
        __syncthreads();
        const float* arow[4];
#pragma unroll
        for (int i = 0; i < 4; i++) {
            int r = ty * 4 + i;
            arow[i] = (kt < 64) ? &R1[r * 68 + kt] : &C2[r * 132 + kt - 64];
        }
#pragma unroll
        for (int k = 0; k < 16; k++) {
            ulonglong2 p0 = *(const ulonglong2*)&WREG[k * 128 + tx * 4];
            ulonglong2 p1 = *(const ulonglong2*)&WREG[k * 128 + 64 + tx * 4];
#pragma unroll
            for (int i = 0; i < 4; i++) {
                ull a = dup2(arow[i][k]);
                ffma2(acc[i][0], a, p0.x);
                ffma2(acc[i][1], a, p0.y);
                ffma2(acc[i][2], a, p1.x);
                ffma2(acc[i][3], a, p1.y);
            }
        }
    }
    __syncthreads();
#pragma unroll
    for (int i = 0; i < 4; i++) {
        int r = ty * 4 + i;
        int iw = i0 + r;
        float gate = (gw[b * NN + iw] > 0.f) ? 1.f : 0.f;
        float4 aw4 = *(const float4*)&R1[r * 68 + tx * 4];
        float aw[4] = {aw4.x, aw4.y, aw4.z, aw4.w};
        float o[4];
#pragma unroll
        for (int j = 0; j < 2; j++) {
            float2 pf = up2(acc[i][j]);
            float2 pu = up2(acc[i][2 + j]);
#pragma unroll
            for (int h = 0; h < 2; h++) {
                int c = tx * 4 + 2 * j + h;
                float fv = sigm((h ? pf.y : pf.x) + bf[c] + gate * g_cF[b * 64 + c]);
                float uv = fmaxf((h ? pu.y : pu.x) + bupd[c] + gate * g_cU[b * 64 + c], 0.f);
                o[2 * j + h] = fmaxf(fv, FTVAL) * aw[2 * j + h] + (1.f - fv) * uv;
            }
        }
        *(float4*)(out + ((size_t)(b * NOUT + iw)) * 64 + tx * 4) =
            make_float4(o[0], o[1], o[2], o[3]);
        *(float4*)&R2[r * 68 + tx * 4] = make_float4(o[0], o[1], o[2], o[3]);
    }
    __syncthreads();
    // ---- phase C: Y = upd @ Wo + bo ----
    {
        int row = tid >> 1, colq = (tid & 1) * 32;
#pragma unroll
        for (int u = 0; u < 8; u++)
            *(float4*)&WREG[row * 68 + colq + u * 4] =
                *(const float4*)(Wo + row * 64 + colq + u * 4);
    }
    __syncthreads();
    ull acc2[4][2];
#pragma unroll
    for (int i = 0; i < 4; i++) { acc2[i][0] = 0ull; acc2[i][1] = 0ull; }
#pragma unroll
    for (int k = 0; k < 64; k++) {
        ulonglong2 wp = *(const ulonglong2*)&WREG[k * 68 + tx * 4];
#pragma unroll
        for (int i = 0; i < 4; i++) {
            ull a = dup2(R2[(ty * 4 + i) * 68 + k]);
            ffma2(acc2[i][0], a, wp.x);
            ffma2(acc2[i][1], a, wp.y);
        }
    }
#pragma unroll
    for (int i = 0; i < 4; i++) {
        int rg = r0 + ty * 4 + i;
        int c = tx * 4;
        float2 p0 = up2(acc2[i][0]), p1 = up2(acc2[i][1]);
        *(float4*)(g_Y + (size_t)rg * 64 + c) =
            make_float4(p0.x + bo[c], p0.y + bo[c + 1], p1.x + bo[c + 2], p1.y + bo[c + 3]);
    }
}

// ================= fused op: aggregate Y + matvec + gates =================
__global__ void __launch_bounds__(256) k_op(const float* __restrict__ opE,
                                            const float* __restrict__ bf2,
                                            const float* __restrict__ bout,
                                            float* __restrict__ out) {
    int rg = blockIdx.x;              // b*128 + o
    int b = rg >> 7, oo = rg & (OO - 1);
    int tid = threadIdx.x;
    __shared__ float part[4][65];
    __shared__ int sdeg[4];
    __shared__ float cat[128];
    __shared__ float vsum[2][128];

    {
        int d = tid & 63, grp = tid >> 6;
        const float* Yb = g_Y + (((size_t)b) << 12) * 64;
        unsigned base = (unsigned)rg * 128;
        float a = 0.f;
        int cnt = 0;
        for (int wi = grp; wi < 128; wi += 4) {
            unsigned bits = g_bits[base + wi];
            cnt += __popc(bits);
            while (bits) {
                int j = wi * 32 + (__ffs(bits) - 1);
                bits &= bits - 1u;
                a += Yb[(size_t)j * 64 + d];
            }
        }
        part[grp][d] = a;
        if (d == 0) sdeg[grp] = cnt;
    }
    __syncthreads();
    if (tid < 64) {
        float s = part[0][tid] + part[1][tid] + part[2][tid] + part[3][tid];
        int deg = sdeg[0] + sdeg[1] + sdeg[2] + sdeg[3];
        cat[64 + tid] = s / ((float)deg + 1e-30f);
        cat[tid] = opE[(size_t)rg * 64 + tid];
    }
    __syncthreads();
    {
        int half = tid >> 7, c = tid & 127;
        const float* Wb = g_Wb2 + (size_t)half * 64 * 128 + c;
        float a0 = 0.f, a1 = 0.f, a2 = 0.f, a3 = 0.f;
        const float* cp = cat + half * 64;
#pragma unroll
        for (int k = 0; k < 64; k += 4) {
            a0 += cp[k] * Wb[(size_t)k * 128];
            a1 += cp[k + 1] * Wb[(size_t)(k + 1) * 128];
            a2 += cp[k + 2] * Wb[(size_t)(k + 2) * 128];
            a3 += cp[k + 3] * Wb[(size_t)(k + 3) * 128];
        }
        vsum[half][c] = (a0 + a1) + (a2 + a3);
    }
    __syncthreads();
    if (tid < 64) {
        float pf = vsum[0][tid] + vsum[1][tid] + bf2[tid];
        float pu = vsum[0][64 + tid] + vsum[1][64 + tid] + bout[tid];
        float fv = sigm(pf);
        float uv = fmaxf(pu, 0.f);
        float e = cat[tid];
        out[((size_t)(b * NOUT + NN + oo)) * 64 + tid] =
            fmaxf(fv, FTVAL) * e + (1.f - fv) * uv;
    }
}

// ---------------- launch ----------------
extern "C" void kernel_launch(void* const* d_in, const int* in_sizes, int n_in,
                              void* d_out, int out_size) {
    (void)in_sizes; (void)n_in; (void)out_size;
    const float* w0   = (const float*)d_in[0];
    const float* w1   = (const float*)d_in[1];
    const float* nh   = (const float*)d_in[2];
    const float* opE  = (const float*)d_in[3];
    const float* wes  = (const float*)d_in[4];
    const float* wem  = (const float*)d_in[5];
    const float* wop  = (const float*)d_in[6];
    const float* ww   = (const float*)d_in[7];
    const float* dp0  = (const float*)d_in[8];
    const float* dp1  = (const float*)d_in[9];
    const float* gw   = (const float*)d_in[10];
    const float* Wg   = (const float*)d_in[11];
    const float* bg   = (const float*)d_in[12];
    const float* Wwk  = (const float*)d_in[13];
    const float* bwk  = (const float*)d_in[14];
    const float* Wws  = (const float*)d_in[15];
    const float* bws  = (const float*)d_in[16];
    const float* Wo   = (const float*)d_in[17];
    const float* bo   = (const float*)d_in[18];
    const float* Wupd = (const float*)d_in[19];
    const float* bupd = (const float*)d_in[20];
    const float* Wf   = (const float*)d_in[21];
    const float* bf   = (const float*)d_in[22];
    const float* Wf2  = (const float*)d_in[23];
    const float* bf2  = (const float*)d_in[24];
    const float* Wout = (const float*)d_in[25];
    const float* bout = (const float*)d_in[26];
    float* out = (float*)d_out;

    k_mega<<<2369, 256>>>(ww, wem, dp0, dp1, w0, w1, wes, wop,
                          Wf, Wupd, Wf2, Wout, Wwk, Wws, nh, Wg, bg);
    k_fu<<<256, 128>>>(w0, w1, gw, bwk, bws, bf, bupd, Wo, bo, out);
    k_op<<<256, 256>>>(opE, bf2, bout, out);
}

// round 11
// speedup vs baseline: 3.2230x; 1.0210x over previous
#include <cuda_runtime.h>
#include <math.h>

#define LL 2048
#define NN 4096
#define OO 128
#define NOUT 4224
#define FTVAL 0.2f

typedef unsigned long long ull;

// ---------------- scratch ----------------
static __device__ float g_aggK[(size_t)2 * NN * 64];
static __device__ float g_aggS[(size_t)2 * NN * 64];
static __device__ float g_gateK[2 * NN];
static __device__ float g_gateS[2 * NN];
static __device__ float g_Wx[64 * 128];     // [Wwk | Wws]
static __device__ float g_Wfu[192 * 128];   // [WfR | WuR]
static __device__ float g_Wb2[128 * 128];   // [Wf2 | Wout(pad)]
static __device__ float g_cF[2 * 64];
static __device__ float g_cU[2 * 64];
static __device__ unsigned g_bits[2 * OO * 128];

// ---------------- helpers ----------------
__device__ __forceinline__ ull dup2(float a) {
    ull d; asm("mov.b64 %0, {%1, %1};" : "=l"(d) : "f"(a)); return d;
}
__device__ __forceinline__ void ffma2(ull &c, ull a, ull b) {
    asm("fma.rn.f32x2 %0, %1, %2, %3;" : "=l"(c) : "l"(a), "l"(b), "l"(c));
}
__device__ __forceinline__ float2 up2(ull v) {
    float2 f; asm("mov.b64 {%0, %1}, %2;" : "=f"(f.x), "=f"(f.y) : "l"(v)); return f;
}
__device__ __forceinline__ float sigm(float x) { return 1.f / (1.f + __expf(-x)); }

// exclusive warp scan; returns exclusive prefix, sets total
__device__ __forceinline__ int wscan_excl(int v, int lane, int &total) {
    int x = v;
#pragma unroll
    for (int d = 1; d < 32; d <<= 1) {
        int y = __shfl_up_sync(0xffffffffu, x, d);
        if (lane >= d) x += y;
    }
    total = __shfl_sync(0xffffffffu, x, 31);
    return x - v;
}

__device__ __forceinline__ unsigned mask8(const float4* src, int lane) {
    float4 v[8];
#pragma unroll
    for (int u = 0; u < 8; u++) v[u] = src[(size_t)u * 32 + lane];
    unsigned m = 0;
#pragma unroll
    for (int u = 0; u < 8; u++) {
        m |= (v[u].x != 0.f ? 1u : 0u) << (4 * u);
        m |= (v[u].y != 0.f ? 1u : 0u) << (4 * u + 1);
        m |= (v[u].z != 0.f ? 1u : 0u) << (4 * u + 2);
        m |= (v[u].w != 0.f ? 1u : 0u) << (4 * u + 3);
    }
    return m;
}

// ================= mega kernel: setup (193) + opbits (128) + agg (2048) =================
__global__ void __launch_bounds__(256) k_mega(
        const float* __restrict__ ww, const float* __restrict__ wem,
        const float* __restrict__ dp0, const float* __restrict__ dp1,
        const float* __restrict__ w0, const float* __restrict__ w1,
        const float* __restrict__ wes, const float* __restrict__ wop,
        const float* __restrict__ Wf, const float* __restrict__ Wupd,
        const float* __restrict__ Wf2, const float* __restrict__ Wout,
        const float* __restrict__ Wwk, const float* __restrict__ Wws,
        const float* __restrict__ nh, const float* __restrict__ Wg,
        const float* __restrict__ bg) {
    int blk = blockIdx.x;
    int tid = threadIdx.x;

    if (blk < 193) {
        int half = tid >> 7, c = tid & 127;
        int ob = blk * 2 + half;   // 0..385
        if (ob < 192) {
            int k = ob;
            float v;
            if (c < 64) { int srcr = (k < 64) ? k : k + 64; v = Wf[srcr * 64 + c]; }
            else v = (k >= 64) ? Wupd[k * 64 + (c - 64)] : 0.f;
            g_Wfu[k * 128 + c] = v;
        } else if (ob < 320) {
            int k = ob - 192;
            float v;
            if (c < 64) v = Wf2[k * 64 + c];
            else v = (k >= 64) ? Wout[(k - 64) * 64 + (c - 64)] : 0.f;
            g_Wb2[k * 128 + c] = v;
        } else if (ob < 384) {
            int k = ob - 320;
            g_Wx[k * 128 + c] = (c < 64) ? Wwk[k * 64 + c] : Wws[k * 64 + (c - 64)];
        } else {
            int b = half;
            __shared__ float gt[2][64], red[2][64], gtn[2][64];
            int d = c;
            if (d < 64) {
                float acc = bg[d];
                for (int k = 0; k < 64; k++) acc += nh[b * 64 + k] * Wg[k * 64 + d];
                gt[half][d] = acc; red[half][d] = acc * acc;
            }
            __syncthreads();
            if (d == 0) { float s = 0.f; for (int k = 0; k < 64; k++) s += red[half][k]; red[half][0] = s; }
            __syncthreads();
            float nrm = sqrtf(red[half][0]);
            if (d < 64) gtn[half][d] = gt[half][d] / (nrm + 1e-30f);
            __syncthreads();
            if (d < 64) {
                float cf = 0.f, cu = 0.f;
                for (int h = 0; h < 64; h++) {
                    float v = gtn[half][h];
                    cf += v * Wf[(64 + h) * 64 + d];
                    cu += v * Wupd[h * 64 + d];
                }
                g_cF[b * 64 + d] = cf;
                g_cU[b * 64 + d] = cu;
            }
        }
        return;
    }
    if (blk < 321) {
        int w = ((blk - 193) * 256 + tid) >> 5;
        int lane = tid & 31;
        int b = w >> 9;
        int rem = w & 511;
        int og = rem >> 7, ng = rem & 127;
        int o = og * 32 + lane;
        const float* wesb = wes + b * NN;
        unsigned word = 0;
        for (int i2 = 0; i2 < 32; i2++) {
            int n = ng * 32 + i2;
            float v = wop[((size_t)(b * NN + n)) * OO + o];
            float s = wesb[n];
            word |= ((v != 0.f && s != 0.f) ? 1u : 0u) << i2;
        }
        g_bits[((b * OO + o) << 7) + ng] = word;
        return;
    }

    // ---- sparse aggregations ----
    __shared__ int buf[8][256];
    int wip = tid >> 5, lane = tid & 31;
    unsigned ltm = (1u << lane) - 1u;
    int* B = buf[wip];
    int ablk = blk - 321;

    if (ablk < 1024) {
        // ---- word_w_k: scan ww (1 scan per 2048 cols), filter by wem, gather ----
        int row = ablk * 8 + wip;
        int b = row >> 12;
        const float4* wwr = (const float4*)(ww + (size_t)row * NN);
        const float* wemr = wem + (size_t)row * NN;
        const float* w0b = w0 + ((size_t)b * LL) * 64;
        const float* w1b = w1 + ((size_t)b * LL) * 64;
        int cnt = 0;
#pragma unroll
        for (int half = 0; half < 2; half++) {
            unsigned ma = mask8(wwr + (size_t)(half * 16) * 32, lane);
            unsigned mb = mask8(wwr + (size_t)(half * 16 + 8) * 32, lane);
            int total;
            int off = wscan_excl(__popc(ma) + __popc(mb), lane, total);
            int pos = cnt + off;
            while (ma) {
                int bs = __ffs(ma) - 1;
                ma &= ma - 1u;
                int j = (half * 16 + (bs >> 2)) * 128 + lane * 4 + (bs & 3);
                if (pos < 256) B[pos] = j;
                pos++;
            }
            while (mb) {
                int bs = __ffs(mb) - 1;
                mb &= mb - 1u;
                int j = (half * 16 + 8 + (bs >> 2)) * 128 + lane * 4 + (bs & 3);
                if (pos < 256) B[pos] = j;
                pos++;
            }
            cnt += total;
        }
        if (cnt > 256) cnt = 256;
        __syncwarp();
        // filter by wem (lane-parallel gathers, re-compact)
        int cnt2 = 0;
        for (int base = 0; base < cnt; base += 32) {
            int t = base + lane;
            int j = (t < cnt) ? B[t] : -1;
            bool val = (j >= 0) && (wemr[j] != 0.f);
            unsigned bal = __ballot_sync(0xffffffffu, val);
            __syncwarp();
            if (val) B[cnt2 + __popc(bal & ltm)] = j;
            cnt2 += __popc(bal);
        }
        __syncwarp();
        // gather (float2 per lane), 8-way unrolled
        float a0 = 0.f, a1 = 0.f, c0 = 0.f, c1 = 0.f;
        int t = 0;
        for (; t + 8 <= cnt2; t += 8) {
            const float2* p[8];
#pragma unroll
            for (int q = 0; q < 8; q++) {
                int j = B[t + q];
                p[q] = (const float2*)((j < LL) ? w0b + (size_t)j * 64
                                                : w1b + (size_t)(j - LL) * 64);
            }
            float2 g[8];
#pragma unroll
            for (int q = 0; q < 8; q++) g[q] = p[q][lane];
#pragma unroll
            for (int q = 0; q < 8; q++) {
                if (q & 1) { c0 += g[q].x; c1 += g[q].y; } else { a0 += g[q].x; a1 += g[q].y; }
            }
        }
        for (; t < cnt2; t++) {
            int j = B[t];
            const float2* p = (const float2*)((j < LL) ? w0b + (size_t)j * 64
                                                       : w1b + (size_t)(j - LL) * 64);
            float2 g = p[lane];
            a0 += g.x; a1 += g.y;
        }
        a0 += c0; a1 += c1;
        float inv = 1.f / ((float)cnt2 + 1e-30f);
        ((float2*)(g_aggK + (size_t)row * 64))[lane] = make_float2(a0 * inv, a1 * inv);
        if (lane == 0) g_gateK[row] = (cnt2 > 0) ? 1.f : 0.f;
    } else {
        // ---- word_w_s: scan depend (1 scan per row), gather ----
        int row = (ablk - 1024) * 8 + wip;
        int b = row >> 12;
        int i = row & (NN - 1);
        const float* mat;
        const float* Xb;
        if (i < LL) {
            mat = dp0 + ((size_t)(b * LL + i)) * LL;
            Xb = w0 + ((size_t)b * LL) * 64;
        } else {
            mat = dp1 + ((size_t)(b * LL + i - LL)) * LL;
            Xb = w1 + ((size_t)b * LL) * 64;
        }
        const float4* m4 = (const float4*)mat;
        unsigned ma = mask8(m4, lane);
        unsigned mb = mask8(m4 + (size_t)8 * 32, lane);
        int total;
        int off = wscan_excl(__popc(ma) + __popc(mb), lane, total);
        int pos = off;
        while (ma) {
            int bs = __ffs(ma) - 1;
            ma &= ma - 1u;
            int j = (bs >> 2) * 128 + lane * 4 + (bs & 3);
            if (pos < 256) B[pos] = j;
            pos++;
        }
        while (mb) {
            int bs = __ffs(mb) - 1;
            mb &= mb - 1u;
            int j = (8 + (bs >> 2)) * 128 + lane * 4 + (bs & 3);
            if (pos < 256) B[pos] = j;
            pos++;
        }
        int cnt = (total > 256) ? 256 : total;
        __syncwarp();
        float a0 = 0.f, a1 = 0.f, c0 = 0.f, c1 = 0.f;
        int t = 0;
        for (; t + 8 <= cnt; t += 8) {
            const float2* p[8];
#pragma unroll
            for (int q = 0; q < 8; q++) p[q] = (const float2*)(Xb + (size_t)B[t + q] * 64);
            float2 g[8];
#pragma unroll
            for (int q = 0; q < 8; q++) g[q] = p[q][lane];
#pragma unroll
            for (int q = 0; q < 8; q++) {
                if (q & 1) { c0 += g[q].x; c1 += g[q].y; } else { a0 += g[q].x; a1 += g[q].y; }
            }
        }
        for (; t < cnt; t++) {
            float2 g = ((const float2*)(Xb + (size_t)B[t] * 64))[lane];
            a0 += g.x; a1 += g.y;
        }
        a0 += c0; a1 += c1;
        float inv = 1.f / ((float)cnt + 1e-30f);
        ((float2*)(g_aggS + (size_t)row * 64))[lane] = make_float2(a0 * inv, a1 * inv);
        if (lane == 0) g_gateS[row] = (cnt > 0) ? 1.f : 0.f;
    }
}

// ================= fused mega-GEMM: 128 threads, 4 rows/thread =================
__global__ void __launch_bounds__(128) k_fu(const float* __restrict__ w0,
                                            const float* __restrict__ w1,
                                            const float* __restrict__ gw,
                                            const float* __restrict__ bwk,
                                            const float* __restrict__ bws,
                                            const float* __restrict__ bf,
                                            const float* __restrict__ bupd,
                                            float* __restrict__ out) {
    __shared__ float SM[2176 + 2176 + 6272];
    float* R1 = SM;            // aggK (A) / allw (B), stride 68
    float* R2 = SM + 2176;     // aggS (A), stride 68
    float* WREG = SM + 4352;   // weight chunk 16x128
    float* C2 = WREG + 2048;   // 32 x stride 132

    int tid = threadIdx.x;
    int tx = tid & 15, ty = tid >> 4;
    int r0 = blockIdx.x * 32;
    int b = r0 >> 12, i0 = r0 & (NN - 1);

    {
        int row = tid >> 2, colq = (tid & 3) * 16;
        const float* sK = g_aggK + (size_t)(r0 + row) * 64 + colq;
        const float* sS = g_aggS + (size_t)(r0 + row) * 64 + colq;
#pragma unroll
        for (int u = 0; u < 4; u++) {
            *(float4*)&R1[row * 68 + colq + u * 4] = *(const float4*)(sK + u * 4);
            *(float4*)&R2[row * 68 + colq + u * 4] = *(const float4*)(sS + u * 4);
        }
    }

    ull acc[4][4];
#pragma unroll
    for (int i = 0; i < 4; i++)
#pragma unroll
        for (int j = 0; j < 4; j++) acc[i][j] = 0ull;

    // ---- phase A: [aggK|aggS] @ [Wwk|Wws] ----
    for (int kt = 0; kt < 64; kt += 16) {
        __syncthreads();
        {
            int row = tid >> 3, col = (tid & 7) * 16;
#pragma unroll
            for (int u = 0; u < 4; u++)
                *(float4*)&WREG[row * 128 + col + u * 4] =
                    *(const float4*)(g_Wx + (kt + row) * 128 + col + u * 4);
        }
        __syncthreads();
#pragma unroll
        for (int k = 0; k < 16; k++) {
            ulonglong2 p0 = *(const ulonglong2*)&WREG[k * 128 + tx * 4];
            ulonglong2 p1 = *(const ulonglong2*)&WREG[k * 128 + 64 + tx * 4];
#pragma unroll
            for (int i = 0; i < 4; i++) {
                int r = ty * 4 + i;
                ull ak = dup2(R1[r * 68 + kt + k]);
                ull as = dup2(R2[r * 68 + kt + k]);
                ffma2(acc[i][0], ak, p0.x);
                ffma2(acc[i][1], ak, p0.y);
                ffma2(acc[i][2], as, p1.x);
                ffma2(acc[i][3], as, p1.y);
            }
        }
    }
#pragma unroll
    for (int i = 0; i < 4; i++) {
        int r = ty * 4 + i;
        float gk = g_gateK[r0 + r], gs = g_gateS[r0 + r];
        float wk[4], ws[4];
#pragma unroll
        for (int j = 0; j < 2; j++) {
            float2 pk = up2(acc[i][j]);
            float2 ps = up2(acc[i][2 + j]);
            int c = tx * 4 + 2 * j;
            wk[2 * j] = pk.x + gk * bwk[c];
            wk[2 * j + 1] = pk.y + gk * bwk[c + 1];
            ws[2 * j] = ps.x + gs * bws[c];
            ws[2 * j + 1] = ps.y + gs * bws[c + 1];
        }
        float sk = 0.f, ss = 0.f;
#pragma unroll
        for (int q = 0; q < 4; q++) { sk += wk[q] * wk[q]; ss += ws[q] * ws[q]; }
#pragma unroll
        for (int d = 8; d; d >>= 1) {
            sk += __shfl_xor_sync(0xffffffffu, sk, d);
            ss += __shfl_xor_sync(0xffffffffu, ss, d);
        }
        float ik = 1.f / (sqrtf(sk) + 1e-30f);
        float is = 1.f / (sqrtf(ss) + 1e-30f);
        *(float4*)&C2[r * 132 + tx * 4] =
            make_float4(wk[0] * ik, wk[1] * ik, wk[2] * ik, wk[3] * ik);
        *(float4*)&C2[r * 132 + 64 + tx * 4] =
            make_float4(ws[0] * is, ws[1] * is, ws[2] * is, ws[3] * is);
    }
    __syncthreads();
    {
        int row = tid >> 2, colq = (tid & 3) * 16;
        int i = i0 + row;
        const float* src = (i < LL) ? (w0 + ((size_t)(b * LL + i)) * 64)
                                    : (w1 + ((size_t)(b * LL + i - LL)) * 64);
#pragma unroll
        for (int u = 0; u < 4; u++)
            *(float4*)&R1[row * 68 + colq + u * 4] = *(const float4*)(src + colq + u * 4);
    }
#pragma unroll
    for (int i = 0; i < 4; i++)
#pragma unroll
        for (int j = 0; j < 4; j++) acc[i][j] = 0ull;

    // ---- phase B: [allw|wk|ws] @ Wfu ----
    for (int kt = 0; kt < 192; kt += 16) {
        __syncthreads();
        {
            int row = tid >> 3, col = (tid & 7) * 16;
#pragma unroll
            for (int u = 0; u < 4; u++)
                *(float4*)&WREG[row * 128 + col + u * 4] =
                    *(const float4*)(g_Wfu + (kt + row) * 128 + col + u * 4);
        }
        __syncthreads();
        const float* arow[4];
#pragma unroll
        for (int i = 0; i < 4; i++) {
            int r = ty * 4 + i;
            arow[i] = (kt < 64) ? &R1[r * 68 + kt] : &C2[r * 132 + kt - 64];
        }
#pragma unroll
        for (int k = 0; k < 16; k++) {
            ulonglong2 p0 = *(const ulonglong2*)&WREG[k * 128 + tx * 4];
            ulonglong2 p1 = *(const ulonglong2*)&WREG[k * 128 + 64 + tx * 4];
#pragma unroll
            for (int i = 0; i < 4; i++) {
                ull a = dup2(arow[i][k]);
                ffma2(acc[i][0], a, p0.x);
                ffma2(acc[i][1], a, p0.y);
                ffma2(acc[i][2], a, p1.x);
                ffma2(acc[i][3], a, p1.y);
            }
        }
    }
    __syncthreads();
#pragma unroll
    for (int i = 0; i < 4; i++) {
        int r = ty * 4 + i;
        int iw = i0 + r;
        float gate = (gw[b * NN + iw] > 0.f) ? 1.f : 0.f;
        float4 aw4 = *(const float4*)&R1[r * 68 + tx * 4];
        float aw[4] = {aw4.x, aw4.y, aw4.z, aw4.w};
        float o[4];
#pragma unroll
        for (int j = 0; j < 2; j++) {
            float2 pf = up2(acc[i][j]);
            float2 pu = up2(acc[i][2 + j]);
#pragma unroll
            for (int h = 0; h < 2; h++) {
                int c = tx * 4 + 2 * j + h;
                float fv = sigm((h ? pf.y : pf.x) + bf[c] + gate * g_cF[b * 64 + c]);
                float uv = fmaxf((h ? pu.y : pu.x) + bupd[c] + gate * g_cU[b * 64 + c], 0.f);
                o[2 * j + h] = fmaxf(fv, FTVAL) * aw[2 * j + h] + (1.f - fv) * uv;
            }
        }
        *(float4*)(out + ((size_t)(b * NOUT + iw)) * 64 + tx * 4) =
            make_float4(o[0], o[1], o[2], o[3]);
    }
}

// ================= fused op: aggregate upd + Wo matvec + Wb2 matvec + gates =================
__global__ void __launch_bounds__(256) k_op(const float* __restrict__ opE,
                                            const float* __restrict__ Wo,
                                            const float* __restrict__ bo,
                                            const float* __restrict__ bf2,
                                            const float* __restrict__ bout,
                                            float* __restrict__ out) {
    int rg = blockIdx.x;              // b*128 + o
    int b = rg >> 7, oo = rg & (OO - 1);
    int tid = threadIdx.x;
    __shared__ float part[4][65];
    __shared__ int sdeg[4];
    __shared__ float aggU[64];
    __shared__ float cat[128];        // [opE row | word_op row]
    __shared__ float v1[4][64];
    __shared__ float vsum[2][128];
    __shared__ float gdeg;

    // phase 1: aggregate word_updated rows (from out) by bitmask
    {
        int d = tid & 63, grp = tid >> 6;
        const float* Ub = out + ((size_t)b * NOUT) * 64;
        unsigned base = (unsigned)rg * 128;
        float a = 0.f;
        int cnt = 0;
        for (int wi = grp; wi < 128; wi += 4) {
            unsigned bits = g_bits[base + wi];
            cnt += __popc(bits);
            while (bits) {
                int j = wi * 32 + (__ffs(bits) - 1);
                bits &= bits - 1u;
                a += Ub[(size_t)j * 64 + d];
            }
        }
        part[grp][d] = a;
        if (d == 0) sdeg[grp] = cnt;
    }
    __syncthreads();
    if (tid < 64) {
        float s = part[0][tid] + part[1][tid] + part[2][tid] + part[3][tid];
        int deg = sdeg[0] + sdeg[1] + sdeg[2] + sdeg[3];
        aggU[tid] = s / ((float)deg + 1e-30f);
        cat[tid] = opE[(size_t)rg * 64 + tid];
        if (tid == 0) gdeg = (deg > 0) ? 1.f : 0.f;
    }
    __syncthreads();
    // phase 1.5: word_op = aggU @ Wo + gdeg*bo  (K split 4x16)
    {
        int c = tid & 63, q = tid >> 6;
        float s = 0.f;
        const float* Wp = Wo + (q * 16) * 64 + c;
        const float* ap = aggU + q * 16;
#pragma unroll
        for (int k = 0; k < 16; k++) s += ap[k] * Wp[k * 64];
        v1[q][c] = s;
    }
    __syncthreads();
    if (tid < 64)
        cat[64 + tid] = v1[0][tid] + v1[1][tid] + v1[2][tid] + v1[3][tid] + gdeg * bo[tid];
    __syncthreads();
    // phase 2: mat-vec  v[c] = sum_k cat[k] * Wb2[k][c], K split in halves
    {
        int half = tid >> 7, c = tid & 127;
        const float* Wb = g_Wb2 + (size_t)half * 64 * 128 + c;
        float a0 = 0.f, a1 = 0.f, a2 = 0.f, a3 = 0.f;
        const float* cp = cat + half * 64;
#pragma unroll
        for (int k = 0; k < 64; k += 4) {
            a0 += cp[k] * Wb[(size_t)k * 128];
            a1 += cp[k + 1] * Wb[(size_t)(k + 1) * 128];
            a2 += cp[k + 2] * Wb[(size_t)(k + 2) * 128];
            a3 += cp[k + 3] * Wb[(size_t)(k + 3) * 128];
        }
        vsum[half][c] = (a0 + a1) + (a2 + a3);
    }
    __syncthreads();
    // phase 3: gates + output
    if (tid < 64) {
        float pf = vsum[0][tid] + vsum[1][tid] + bf2[tid];
        float pu = vsum[0][64 + tid] + vsum[1][64 + tid] + bout[tid];
        float fv = sigm(pf);
        float uv = fmaxf(pu, 0.f);
        float e = cat[tid];
        out[((size_t)(b * NOUT + NN + oo)) * 64 + tid] =
            fmaxf(fv, FTVAL) * e + (1.f - fv) * uv;
    }
}

// ---------------- launch ----------------
extern "C" void kernel_launch(void* const* d_in, const int* in_sizes, int n_in,
                              void* d_out, int out_size) {
    (void)in_sizes; (void)n_in; (void)out_size;
    const float* w0   = (const float*)d_in[0];
    const float* w1   = (const float*)d_in[1];
    const float* nh   = (const float*)d_in[2];
    const float* opE  = (const float*)d_in[3];
    const float* wes  = (const float*)d_in[4];
    const float* wem  = (const float*)d_in[5];
    const float* wop  = (const float*)d_in[6];
    const float* ww   = (const float*)d_in[7];
    const float* dp0  = (const float*)d_in[8];
    const float* dp1  = (const float*)d_in[9];
    const float* gw   = (const float*)d_in[10];
    const float* Wg   = (const float*)d_in[11];
    const float* bg   = (const float*)d_in[12];
    const float* Wwk  = (const float*)d_in[13];
    const float* bwk  = (const float*)d_in[14];
    const float* Wws  = (const float*)d_in[15];
    const float* bws  = (const float*)d_in[16];
    const float* Wo   = (const float*)d_in[17];
    const float* bo   = (const float*)d_in[18];
    const float* Wupd = (const float*)d_in[19];
    const float* bupd = (const float*)d_in[20];
    const float* Wf   = (const float*)d_in[21];
    const float* bf   = (const float*)d_in[22];
    const float* Wf2  = (const float*)d_in[23];
    const float* bf2  = (const float*)d_in[24];
    const float* Wout = (const float*)d_in[25];
    const float* bout = (const float*)d_in[26];
    float* out = (float*)d_out;

    k_mega<<<2369, 256>>>(ww, wem, dp0, dp1, w0, w1, wes, wop,
                          Wf, Wupd, Wf2, Wout, Wwk, Wws, nh, Wg, bg);
    k_fu<<<256, 128>>>(w0, w1, gw, bwk, bws, bf, bupd, out);
    k_op<<<256, 256>>>(opE, Wo, bo, bf2, bout, out);
}